// round 3
// baseline (speedup 1.0000x reference)
#include <cuda_runtime.h>

#define BB 8
#define MM 4096
#define EE 1024
#define DD 128
#define NCAT 64

// ---------------- scratch (no allocations allowed) ----------------
__device__ float g_Wt_att[DD * DD];          // Wt[k][j] = W_att[j][k]
__device__ float g_Wt_proj[DD * DD];         // Wt[k][j] = W_proj[j][k]
__device__ float g_scores[BB * MM * DD];     // node_scores (b,m,d)
__device__ float g_agg[BB * EE * DD];        // agg, later overwritten by agg*attn
__device__ float g_esc[BB * EE * DD];        // edge_scores
__device__ float g_edgefeat[BB * EE * DD];   // edge_feat
__device__ float g_colsum[BB * DD];          // softmax denom over e, per (b,d)
__device__ float g_att[BB * EE];             // edge pooling attention logits
__device__ float g_pooled[BB * DD];

// ---------------- K0: transpose both weight matrices ----------------
__global__ void transpose_w(const float* __restrict__ Wa, const float* __restrict__ Wp) {
    int k = blockIdx.x & (DD - 1);
    const float* src = (blockIdx.x < DD) ? Wa : Wp;
    float* dst = (blockIdx.x < DD) ? g_Wt_att : g_Wt_proj;
    int j = threadIdx.x;
    dst[k * DD + j] = src[j * DD + k];
}

// ---------------- rowgemm: out[r][j] = sum_k X[r][k] * Wt[k][j] ----------------
// PHASE 0: X = node_feats (host-passed), Wt = g_Wt_att,  out = g_scores
// PHASE 1: X = g_agg (device symbol — must be resolved IN DEVICE CODE, never
//          passed from host: the host shadow address silently resolves via
//          GB300 ATS to host .bss zeros), Wt = g_Wt_proj, out = g_edgefeat,
//          plus att-dot epilogue.
// Block: 256 thr (tx 0..31 -> 4 d each; ty 0..7 -> 8 rows each), tile 64 x 128.
template <int PHASE>
__global__ __launch_bounds__(256) void rowgemm(const float* __restrict__ Xext,
                                               const float* __restrict__ attw) {
    __shared__ float WtS[32 * 128];
    __shared__ float fsh[64 * 33];
    const float* __restrict__ X = (PHASE == 0) ? Xext : g_agg;   // FIX: device-side symbol resolution
    const float* __restrict__ Wt = (PHASE == 0) ? g_Wt_att : g_Wt_proj;
    float* __restrict__ out = (PHASE == 0) ? g_scores : g_edgefeat;

    int tid = threadIdx.x;
    int tx = tid & 31;
    int ty = tid >> 5;
    int row0 = blockIdx.x * 64;

    float acc[8][4];
#pragma unroll
    for (int i = 0; i < 8; i++)
#pragma unroll
        for (int c = 0; c < 4; c++) acc[i][c] = 0.f;

    for (int kc = 0; kc < DD; kc += 32) {
        // load 32x128 Wt tile (coalesced, conflict-free f4 stores)
#pragma unroll
        for (int i = 0; i < 4; i++) {
            int slot = tid + i * 256;      // 0..1023 float4 slots
            int k = slot >> 5;
            int j4 = slot & 31;
            float4 v = *reinterpret_cast<const float4*>(&Wt[(kc + k) * DD + j4 * 4]);
            *reinterpret_cast<float4*>(&WtS[k * 128 + j4 * 4]) = v;
        }
        // load 64x32 X tile, pitch 33 (scalar stores, conflict-free)
#pragma unroll
        for (int i = 0; i < 2; i++) {
            int slot = tid + i * 256;      // 0..511
            int r = slot >> 3;
            int kq = slot & 7;
            float4 v = *reinterpret_cast<const float4*>(&X[(size_t)(row0 + r) * DD + kc + kq * 4]);
            fsh[r * 33 + kq * 4 + 0] = v.x;
            fsh[r * 33 + kq * 4 + 1] = v.y;
            fsh[r * 33 + kq * 4 + 2] = v.z;
            fsh[r * 33 + kq * 4 + 3] = v.w;
        }
        __syncthreads();
#pragma unroll
        for (int k = 0; k < 32; k++) {
            float4 w4 = *reinterpret_cast<const float4*>(&WtS[k * 128 + tx * 4]);
#pragma unroll
            for (int i = 0; i < 8; i++) {
                float f = fsh[(ty * 8 + i) * 33 + k];
                acc[i][0] = fmaf(f, w4.x, acc[i][0]);
                acc[i][1] = fmaf(f, w4.y, acc[i][1]);
                acc[i][2] = fmaf(f, w4.z, acc[i][2]);
                acc[i][3] = fmaf(f, w4.w, acc[i][3]);
            }
        }
        __syncthreads();
    }

    float4 aw = make_float4(0.f, 0.f, 0.f, 0.f);
    if (PHASE == 1) aw = *reinterpret_cast<const float4*>(&attw[tx * 4]);

#pragma unroll
    for (int i = 0; i < 8; i++) {
        int r = row0 + ty * 8 + i;
        float4 v = make_float4(acc[i][0], acc[i][1], acc[i][2], acc[i][3]);
        *reinterpret_cast<float4*>(&out[(size_t)r * DD + tx * 4]) = v;
        if (PHASE == 1) {
            // a[b,e] = dot(edge_feat[r,:], ec_att_w)
            float p = v.x * aw.x + v.y * aw.y + v.z * aw.z + v.w * aw.w;
#pragma unroll
            for (int off = 16; off > 0; off >>= 1)
                p += __shfl_xor_sync(0xffffffffu, p, off);
            if (tx == 0) g_att[r] = p;
        }
    }
}

// ---------------- K2: fused dual contraction over m ----------------
// agg[b,e,d] = sum_m inc[b,m,e]*feats[b,m,d];  esc[b,e,d] = sum_m inc[b,m,e]*scores[b,m,d]
// Block: 256 thr (tx 0..31 -> 4 d; ty 0..7 -> 4 e), tile 32 e x 128 d, one pass over M.
__global__ __launch_bounds__(256) void dual_contract(const float* __restrict__ inc,
                                                     const float* __restrict__ feats) {
    __shared__ float incS[32 * 40];   // [k][e] pitch 40 (16B-aligned rows)
    __shared__ float featS[32 * 128];
    __shared__ float scoS[32 * 128];

    int tid = threadIdx.x;
    int tx = tid & 31;
    int ty = tid >> 5;
    int e0 = blockIdx.x * 32;
    int b = blockIdx.y;

    const float* __restrict__ incB = inc + (size_t)b * MM * EE;
    const float* __restrict__ featB = feats + (size_t)b * MM * DD;
    const float* __restrict__ scoB = g_scores + (size_t)b * MM * DD;

    float accA[4][4], accS[4][4];
#pragma unroll
    for (int i = 0; i < 4; i++)
#pragma unroll
        for (int c = 0; c < 4; c++) { accA[i][c] = 0.f; accS[i][c] = 0.f; }

    for (int mc = 0; mc < MM; mc += 32) {
        {   // inc tile: 32 m x 32 e  (one f4 per thread)
            int k = tid >> 3;
            int e4 = tid & 7;
            float4 v = *reinterpret_cast<const float4*>(&incB[(size_t)(mc + k) * EE + e0 + e4 * 4]);
            *reinterpret_cast<float4*>(&incS[k * 40 + e4 * 4]) = v;
        }
#pragma unroll
        for (int i = 0; i < 4; i++) {   // feats/scores tiles: 32 m x 128 d
            int slot = tid + i * 256;
            int k = slot >> 5;
            int d4 = slot & 31;
            *reinterpret_cast<float4*>(&featS[k * 128 + d4 * 4]) =
                *reinterpret_cast<const float4*>(&featB[(size_t)(mc + k) * DD + d4 * 4]);
            *reinterpret_cast<float4*>(&scoS[k * 128 + d4 * 4]) =
                *reinterpret_cast<const float4*>(&scoB[(size_t)(mc + k) * DD + d4 * 4]);
        }
        __syncthreads();
#pragma unroll
        for (int k = 0; k < 32; k++) {
            float4 in4 = *reinterpret_cast<const float4*>(&incS[k * 40 + ty * 4]);
            float4 f4 = *reinterpret_cast<const float4*>(&featS[k * 128 + tx * 4]);
            float4 s4 = *reinterpret_cast<const float4*>(&scoS[k * 128 + tx * 4]);
            float ia[4] = {in4.x, in4.y, in4.z, in4.w};
            float fa[4] = {f4.x, f4.y, f4.z, f4.w};
            float sa[4] = {s4.x, s4.y, s4.z, s4.w};
#pragma unroll
            for (int ei = 0; ei < 4; ei++)
#pragma unroll
                for (int ci = 0; ci < 4; ci++) {
                    accA[ei][ci] = fmaf(ia[ei], fa[ci], accA[ei][ci]);
                    accS[ei][ci] = fmaf(ia[ei], sa[ci], accS[ei][ci]);
                }
        }
        __syncthreads();
    }

#pragma unroll
    for (int ei = 0; ei < 4; ei++) {
        int e = e0 + ty * 4 + ei;
        size_t o = ((size_t)b * EE + e) * DD + tx * 4;
        *reinterpret_cast<float4*>(&g_agg[o]) =
            make_float4(accA[ei][0], accA[ei][1], accA[ei][2], accA[ei][3]);
        *reinterpret_cast<float4*>(&g_esc[o]) =
            make_float4(accS[ei][0], accS[ei][1], accS[ei][2], accS[ei][3]);
    }
}

// ---------------- K3a: softmax denominator over e per (b,d) ----------------
// No max-subtraction: edge scores have std ~8.3; exp overflow needs >10 sigma.
__global__ __launch_bounds__(1024) void colsum_kernel() {
    int b = blockIdx.x;
    int d = threadIdx.x & 127;
    int ci = threadIdx.x >> 7;   // 8 e-chunks of 128
    __shared__ float red[8 * 128];
    const float* __restrict__ esc = g_esc + (size_t)b * EE * DD;
    float s = 0.f;
#pragma unroll 4
    for (int j = 0; j < 128; j++) {
        int e = ci * 128 + j;
        s += __expf(esc[(size_t)e * DD + d]);
    }
    red[ci * 128 + d] = s;
    __syncthreads();
    if (ci == 0) {
        float t = 0.f;
#pragma unroll
        for (int c2 = 0; c2 < 8; c2++) t += red[c2 * 128 + d];
        g_colsum[b * DD + d] = t;
    }
}

// ---------------- K3b: g_agg <- agg * exp(esc)/colsum  (= agg * attn) ----------------
__global__ __launch_bounds__(256) void attn_mul() {
    int idx4 = blockIdx.x * 256 + threadIdx.x;
    size_t base = (size_t)idx4 * 4;
    int b = (int)(base >> 17);          // / (E*D)
    int d = (int)(base & 127);
    float4 a = *reinterpret_cast<const float4*>(&g_agg[base]);
    float4 s = *reinterpret_cast<const float4*>(&g_esc[base]);
    float4 cs = *reinterpret_cast<const float4*>(&g_colsum[b * DD + d]);
    a.x = a.x * __expf(s.x) / cs.x;
    a.y = a.y * __expf(s.y) / cs.y;
    a.z = a.z * __expf(s.z) / cs.z;
    a.w = a.w * __expf(s.w) / cs.w;
    *reinterpret_cast<float4*>(&g_agg[base]) = a;
}

// ---------------- K5: edge softmax pooling -> pooled[b,d] ----------------
__global__ __launch_bounds__(256) void pool_kernel() {
    int b = blockIdx.x;
    int tid = threadIdx.x;
    __shared__ float ew[EE];
    __shared__ float red[256];
    __shared__ float part[256];

    float s = 0.f;
    for (int e = tid; e < EE; e += 256) {
        float w = __expf(g_att[b * EE + e]);
        ew[e] = w;
        s += w;
    }
    red[tid] = s;
    __syncthreads();
#pragma unroll
    for (int st = 128; st > 0; st >>= 1) {
        if (tid < st) red[tid] += red[tid + st];
        __syncthreads();
    }
    float S = red[0];

    int d = tid & 127;
    int h = tid >> 7;
    const float* __restrict__ ef = g_edgefeat + (size_t)b * EE * DD;
    float acc = 0.f;
    for (int e = h * 512; e < h * 512 + 512; e++)
        acc = fmaf(ef[(size_t)e * DD + d], ew[e], acc);
    part[tid] = acc;
    __syncthreads();
    if (tid < 128) g_pooled[b * DD + tid] = (part[tid] + part[tid + 128]) / S;
}

// ---------------- K6: out = pooled@ec_proj^T + b; logits = out@fc^T + fc_b ----------------
__global__ __launch_bounds__(128) void head_kernel(const float* __restrict__ ec_proj_w,
                                                   const float* __restrict__ ec_proj_b,
                                                   const float* __restrict__ fc_w,
                                                   const float* __restrict__ fc_b,
                                                   float* __restrict__ out) {
    int b = blockIdx.x;
    int d = threadIdx.x;
    __shared__ float p[DD];
    __shared__ float o[DD];
    p[d] = g_pooled[b * DD + d];
    __syncthreads();
    float acc = ec_proj_b[d];
#pragma unroll 4
    for (int k = 0; k < DD; k++) acc = fmaf(p[k], ec_proj_w[d * DD + k], acc);
    o[d] = acc;
    __syncthreads();
    if (d < NCAT) {
        float l = fc_b[d];
#pragma unroll 4
        for (int k = 0; k < DD; k++) l = fmaf(o[k], fc_w[d * DD + k], l);
        out[b * NCAT + d] = l;
    }
}

// ---------------- launch ----------------
extern "C" void kernel_launch(void* const* d_in, const int* in_sizes, int n_in,
                              void* d_out, int out_size) {
    const float* node_feats = (const float*)d_in[0];
    const float* inc_mat    = (const float*)d_in[1];
    const float* W_att      = (const float*)d_in[2];
    const float* W_proj     = (const float*)d_in[3];
    const float* ec_att_w   = (const float*)d_in[4];
    const float* ec_proj_w  = (const float*)d_in[5];
    const float* ec_proj_b  = (const float*)d_in[6];
    const float* fc_w       = (const float*)d_in[7];
    const float* fc_b       = (const float*)d_in[8];
    float* out = (float*)d_out;

    transpose_w<<<2 * DD, DD>>>(W_att, W_proj);
    rowgemm<0><<<(BB * MM) / 64, 256>>>(node_feats, nullptr);       // node_scores
    dual_contract<<<dim3(EE / 32, BB), 256>>>(inc_mat, node_feats); // agg + edge_scores
    colsum_kernel<<<BB, 1024>>>();                                  // softmax denom over e
    attn_mul<<<(BB * EE * DD) / 1024, 256>>>();                     // agg *= attn
    rowgemm<1><<<(BB * EE) / 64, 256>>>(nullptr, ec_att_w);         // edge_feat + att dots (X = g_agg resolved device-side)
    pool_kernel<<<BB, 256>>>();                                     // pooled
    head_kernel<<<BB, DD>>>(ec_proj_w, ec_proj_b, fc_w, fc_b, out); // logits
}

// round 4
// speedup vs baseline: 1.0019x; 1.0019x over previous
#include <cuda_runtime.h>

#define BB 8
#define MM 4096
#define EE 1024
#define DD 128
#define NCAT 64

// ---------------- scratch (no allocations allowed) ----------------
__device__ float g_Wt_att[DD * DD];          // Wt[k][j] = W_att[j][k]
__device__ float g_Wt_proj[DD * DD];         // Wt[k][j] = W_proj[j][k]
__device__ float g_scores[BB * MM * DD];     // node_scores (b,m,d)
__device__ float g_agg[BB * EE * DD];        // agg, later overwritten by agg*attn
__device__ float g_esc[BB * EE * DD];        // edge_scores
__device__ float g_edgefeat[BB * EE * DD];   // edge_feat
__device__ float g_colsum[BB * DD];          // softmax denom over e, per (b,d)
__device__ float g_att[BB * EE];             // edge pooling attention logits
__device__ float g_pooled[BB * DD];

// ---------------- K0: transpose both weight matrices ----------------
__global__ void transpose_w(const float* __restrict__ Wa, const float* __restrict__ Wp) {
    int k = blockIdx.x & (DD - 1);
    const float* src = (blockIdx.x < DD) ? Wa : Wp;
    float* dst = (blockIdx.x < DD) ? g_Wt_att : g_Wt_proj;
    int j = threadIdx.x;
    dst[k * DD + j] = src[j * DD + k];
}

// ---------------- rowgemm: out[r][j] = sum_k X[r][k] * Wt[k][j] ----------------
// PHASE 0: X = node_feats (host-passed), Wt = g_Wt_att,  out = g_scores
// PHASE 1: X = g_agg (device symbol — must be resolved IN DEVICE CODE, never
//          passed from host: the host shadow address silently resolves via
//          GB300 ATS to host .bss zeros), Wt = g_Wt_proj, out = g_edgefeat,
//          plus att-dot epilogue.
// Block: 256 thr (tx 0..31 -> 4 d each; ty 0..7 -> 8 rows each), tile 64 x 128.
template <int PHASE>
__global__ __launch_bounds__(256) void rowgemm(const float* __restrict__ Xext,
                                               const float* __restrict__ attw) {
    __shared__ float WtS[32 * 128];
    __shared__ float fsh[64 * 33];
    const float* __restrict__ X = (PHASE == 0) ? Xext : g_agg;   // FIX: device-side symbol resolution
    const float* __restrict__ Wt = (PHASE == 0) ? g_Wt_att : g_Wt_proj;
    float* __restrict__ out = (PHASE == 0) ? g_scores : g_edgefeat;

    int tid = threadIdx.x;
    int tx = tid & 31;
    int ty = tid >> 5;
    int row0 = blockIdx.x * 64;

    float acc[8][4];
#pragma unroll
    for (int i = 0; i < 8; i++)
#pragma unroll
        for (int c = 0; c < 4; c++) acc[i][c] = 0.f;

    for (int kc = 0; kc < DD; kc += 32) {
        // load 32x128 Wt tile (coalesced, conflict-free f4 stores)
#pragma unroll
        for (int i = 0; i < 4; i++) {
            int slot = tid + i * 256;      // 0..1023 float4 slots
            int k = slot >> 5;
            int j4 = slot & 31;
            float4 v = *reinterpret_cast<const float4*>(&Wt[(kc + k) * DD + j4 * 4]);
            *reinterpret_cast<float4*>(&WtS[k * 128 + j4 * 4]) = v;
        }
        // load 64x32 X tile, pitch 33 (scalar stores, conflict-free)
#pragma unroll
        for (int i = 0; i < 2; i++) {
            int slot = tid + i * 256;      // 0..511
            int r = slot >> 3;
            int kq = slot & 7;
            float4 v = *reinterpret_cast<const float4*>(&X[(size_t)(row0 + r) * DD + kc + kq * 4]);
            fsh[r * 33 + kq * 4 + 0] = v.x;
            fsh[r * 33 + kq * 4 + 1] = v.y;
            fsh[r * 33 + kq * 4 + 2] = v.z;
            fsh[r * 33 + kq * 4 + 3] = v.w;
        }
        __syncthreads();
#pragma unroll
        for (int k = 0; k < 32; k++) {
            float4 w4 = *reinterpret_cast<const float4*>(&WtS[k * 128 + tx * 4]);
#pragma unroll
            for (int i = 0; i < 8; i++) {
                float f = fsh[(ty * 8 + i) * 33 + k];
                acc[i][0] = fmaf(f, w4.x, acc[i][0]);
                acc[i][1] = fmaf(f, w4.y, acc[i][1]);
                acc[i][2] = fmaf(f, w4.z, acc[i][2]);
                acc[i][3] = fmaf(f, w4.w, acc[i][3]);
            }
        }
        __syncthreads();
    }

    float4 aw = make_float4(0.f, 0.f, 0.f, 0.f);
    if (PHASE == 1) aw = *reinterpret_cast<const float4*>(&attw[tx * 4]);

#pragma unroll
    for (int i = 0; i < 8; i++) {
        int r = row0 + ty * 8 + i;
        float4 v = make_float4(acc[i][0], acc[i][1], acc[i][2], acc[i][3]);
        *reinterpret_cast<float4*>(&out[(size_t)r * DD + tx * 4]) = v;
        if (PHASE == 1) {
            // a[b,e] = dot(edge_feat[r,:], ec_att_w)
            float p = v.x * aw.x + v.y * aw.y + v.z * aw.z + v.w * aw.w;
#pragma unroll
            for (int off = 16; off > 0; off >>= 1)
                p += __shfl_xor_sync(0xffffffffu, p, off);
            if (tx == 0) g_att[r] = p;
        }
    }
}

// ---------------- K2: fused dual contraction over m ----------------
// agg[b,e,d] = sum_m inc[b,m,e]*feats[b,m,d];  esc[b,e,d] = sum_m inc[b,m,e]*scores[b,m,d]
// Block: 256 thr (tx 0..31 -> 4 d; ty 0..7 -> 4 e), tile 32 e x 128 d, one pass over M.
__global__ __launch_bounds__(256) void dual_contract(const float* __restrict__ inc,
                                                     const float* __restrict__ feats) {
    __shared__ float incS[32 * 40];   // [k][e] pitch 40 (16B-aligned rows)
    __shared__ float featS[32 * 128];
    __shared__ float scoS[32 * 128];

    int tid = threadIdx.x;
    int tx = tid & 31;
    int ty = tid >> 5;
    int e0 = blockIdx.x * 32;
    int b = blockIdx.y;

    const float* __restrict__ incB = inc + (size_t)b * MM * EE;
    const float* __restrict__ featB = feats + (size_t)b * MM * DD;
    const float* __restrict__ scoB = g_scores + (size_t)b * MM * DD;

    float accA[4][4], accS[4][4];
#pragma unroll
    for (int i = 0; i < 4; i++)
#pragma unroll
        for (int c = 0; c < 4; c++) { accA[i][c] = 0.f; accS[i][c] = 0.f; }

    for (int mc = 0; mc < MM; mc += 32) {
        {   // inc tile: 32 m x 32 e  (one f4 per thread)
            int k = tid >> 3;
            int e4 = tid & 7;
            float4 v = *reinterpret_cast<const float4*>(&incB[(size_t)(mc + k) * EE + e0 + e4 * 4]);
            *reinterpret_cast<float4*>(&incS[k * 40 + e4 * 4]) = v;
        }
#pragma unroll
        for (int i = 0; i < 4; i++) {   // feats/scores tiles: 32 m x 128 d
            int slot = tid + i * 256;
            int k = slot >> 5;
            int d4 = slot & 31;
            *reinterpret_cast<float4*>(&featS[k * 128 + d4 * 4]) =
                *reinterpret_cast<const float4*>(&featB[(size_t)(mc + k) * DD + d4 * 4]);
            *reinterpret_cast<float4*>(&scoS[k * 128 + d4 * 4]) =
                *reinterpret_cast<const float4*>(&scoB[(size_t)(mc + k) * DD + d4 * 4]);
        }
        __syncthreads();
#pragma unroll
        for (int k = 0; k < 32; k++) {
            float4 in4 = *reinterpret_cast<const float4*>(&incS[k * 40 + ty * 4]);
            float4 f4 = *reinterpret_cast<const float4*>(&featS[k * 128 + tx * 4]);
            float4 s4 = *reinterpret_cast<const float4*>(&scoS[k * 128 + tx * 4]);
            float ia[4] = {in4.x, in4.y, in4.z, in4.w};
            float fa[4] = {f4.x, f4.y, f4.z, f4.w};
            float sa[4] = {s4.x, s4.y, s4.z, s4.w};
#pragma unroll
            for (int ei = 0; ei < 4; ei++)
#pragma unroll
                for (int ci = 0; ci < 4; ci++) {
                    accA[ei][ci] = fmaf(ia[ei], fa[ci], accA[ei][ci]);
                    accS[ei][ci] = fmaf(ia[ei], sa[ci], accS[ei][ci]);
                }
        }
        __syncthreads();
    }

#pragma unroll
    for (int ei = 0; ei < 4; ei++) {
        int e = e0 + ty * 4 + ei;
        size_t o = ((size_t)b * EE + e) * DD + tx * 4;
        *reinterpret_cast<float4*>(&g_agg[o]) =
            make_float4(accA[ei][0], accA[ei][1], accA[ei][2], accA[ei][3]);
        *reinterpret_cast<float4*>(&g_esc[o]) =
            make_float4(accS[ei][0], accS[ei][1], accS[ei][2], accS[ei][3]);
    }
}

// ---------------- K3a: softmax denominator over e per (b,d) ----------------
// No max-subtraction: edge scores have std ~8.3; exp overflow needs >10 sigma.
__global__ __launch_bounds__(1024) void colsum_kernel() {
    int b = blockIdx.x;
    int d = threadIdx.x & 127;
    int ci = threadIdx.x >> 7;   // 8 e-chunks of 128
    __shared__ float red[8 * 128];
    const float* __restrict__ esc = g_esc + (size_t)b * EE * DD;
    float s = 0.f;
#pragma unroll 4
    for (int j = 0; j < 128; j++) {
        int e = ci * 128 + j;
        s += __expf(esc[(size_t)e * DD + d]);
    }
    red[ci * 128 + d] = s;
    __syncthreads();
    if (ci == 0) {
        float t = 0.f;
#pragma unroll
        for (int c2 = 0; c2 < 8; c2++) t += red[c2 * 128 + d];
        g_colsum[b * DD + d] = t;
    }
}

// ---------------- K3b: g_agg <- agg * exp(esc)/colsum  (= agg * attn) ----------------
__global__ __launch_bounds__(256) void attn_mul() {
    int idx4 = blockIdx.x * 256 + threadIdx.x;
    size_t base = (size_t)idx4 * 4;
    int b = (int)(base >> 17);          // / (E*D)
    int d = (int)(base & 127);
    float4 a = *reinterpret_cast<const float4*>(&g_agg[base]);
    float4 s = *reinterpret_cast<const float4*>(&g_esc[base]);
    float4 cs = *reinterpret_cast<const float4*>(&g_colsum[b * DD + d]);
    a.x = a.x * __expf(s.x) / cs.x;
    a.y = a.y * __expf(s.y) / cs.y;
    a.z = a.z * __expf(s.z) / cs.z;
    a.w = a.w * __expf(s.w) / cs.w;
    *reinterpret_cast<float4*>(&g_agg[base]) = a;
}

// ---------------- K5: edge softmax pooling -> pooled[b,d] ----------------
__global__ __launch_bounds__(256) void pool_kernel() {
    int b = blockIdx.x;
    int tid = threadIdx.x;
    __shared__ float ew[EE];
    __shared__ float red[256];
    __shared__ float part[256];

    float s = 0.f;
    for (int e = tid; e < EE; e += 256) {
        float w = __expf(g_att[b * EE + e]);
        ew[e] = w;
        s += w;
    }
    red[tid] = s;
    __syncthreads();
#pragma unroll
    for (int st = 128; st > 0; st >>= 1) {
        if (tid < st) red[tid] += red[tid + st];
        __syncthreads();
    }
    float S = red[0];

    int d = tid & 127;
    int h = tid >> 7;
    const float* __restrict__ ef = g_edgefeat + (size_t)b * EE * DD;
    float acc = 0.f;
    for (int e = h * 512; e < h * 512 + 512; e++)
        acc = fmaf(ef[(size_t)e * DD + d], ew[e], acc);
    part[tid] = acc;
    __syncthreads();
    if (tid < 128) g_pooled[b * DD + tid] = (part[tid] + part[tid + 128]) / S;
}

// ---------------- K6: out = pooled@ec_proj^T + b; logits = out@fc^T + fc_b ----------------
__global__ __launch_bounds__(128) void head_kernel(const float* __restrict__ ec_proj_w,
                                                   const float* __restrict__ ec_proj_b,
                                                   const float* __restrict__ fc_w,
                                                   const float* __restrict__ fc_b,
                                                   float* __restrict__ out) {
    int b = blockIdx.x;
    int d = threadIdx.x;
    __shared__ float p[DD];
    __shared__ float o[DD];
    p[d] = g_pooled[b * DD + d];
    __syncthreads();
    float acc = ec_proj_b[d];
#pragma unroll 4
    for (int k = 0; k < DD; k++) acc = fmaf(p[k], ec_proj_w[d * DD + k], acc);
    o[d] = acc;
    __syncthreads();
    if (d < NCAT) {
        float l = fc_b[d];
#pragma unroll 4
        for (int k = 0; k < DD; k++) l = fmaf(o[k], fc_w[d * DD + k], l);
        out[b * NCAT + d] = l;
    }
}

// ---------------- launch ----------------
extern "C" void kernel_launch(void* const* d_in, const int* in_sizes, int n_in,
                              void* d_out, int out_size) {
    const float* node_feats = (const float*)d_in[0];
    const float* inc_mat    = (const float*)d_in[1];
    const float* W_att      = (const float*)d_in[2];
    const float* W_proj     = (const float*)d_in[3];
    const float* ec_att_w   = (const float*)d_in[4];
    const float* ec_proj_w  = (const float*)d_in[5];
    const float* ec_proj_b  = (const float*)d_in[6];
    const float* fc_w       = (const float*)d_in[7];
    const float* fc_b       = (const float*)d_in[8];
    float* out = (float*)d_out;

    transpose_w<<<2 * DD, DD>>>(W_att, W_proj);
    rowgemm<0><<<(BB * MM) / 64, 256>>>(node_feats, nullptr);       // node_scores
    dual_contract<<<dim3(EE / 32, BB), 256>>>(inc_mat, node_feats); // agg + edge_scores
    colsum_kernel<<<BB, 1024>>>();                                  // softmax denom over e
    attn_mul<<<(BB * EE * DD) / 1024, 256>>>();                     // agg *= attn
    rowgemm<1><<<(BB * EE) / 64, 256>>>(nullptr, ec_att_w);         // edge_feat + att dots (X = g_agg resolved device-side)
    pool_kernel<<<BB, 256>>>();                                     // pooled
    head_kernel<<<BB, DD>>>(ec_proj_w, ec_proj_b, fc_w, fc_b, out); // logits
}

// round 8
// speedup vs baseline: 3.1528x; 3.1469x over previous
#include <cuda_runtime.h>
#include <cuda_bf16.h>
#include <cstdint>

#define BB 8
#define MM 4096
#define EE 1024
#define DD 128
#define NCAT 64

#define KCH 64
#define NKC (MM / KCH)          // 64
#define NKH 2
#define NCHUNK (NKC / NKH)      // 32
#define A_TILE_BYTES (128 * KCH * 2)                    // 16384
#define B_TILE_BYTES (DD * KCH * 2)                     // 16384
#define STAGE_BYTES (A_TILE_BYTES + 3 * B_TILE_BYTES)   // 65536
#define DYN_SMEM (2 * STAGE_BYTES)                      // 131072

__device__ __align__(128) char  g_A[(size_t)BB * 8 * NKC * A_TILE_BYTES];
__device__ __align__(128) char  g_Bs[(size_t)BB * NKC * 3 * B_TILE_BYTES];
__device__ __align__(128) float g_aggp[NKH * BB * EE * DD];
__device__ float g_Wt_att[DD * DD];
__device__ float g_Wt_proj[DD * DD];
__device__ float g_agg[BB * EE * DD];
__device__ float g_esc[BB * EE * DD];
__device__ float g_edgefeat[BB * EE * DD];
__device__ float g_colpart[BB * 8 * DD];
__device__ float g_colsum[BB * DD];
__device__ float g_att[BB * EE];
__device__ float g_pooled[BB * DD];

__device__ __forceinline__ uint32_t smem_u32(const void* p) {
    uint32_t a;
    asm("{ .reg .u64 t; cvta.to.shared.u64 t, %1; cvt.u32.u64 %0, t; }" : "=r"(a) : "l"(p));
    return a;
}
#define SWZ128(off) ((off) ^ (((off) >> 3) & 0x70))

__device__ __forceinline__ void cpasync16(uint32_t s, const void* g) {
    asm volatile("cp.async.cg.shared.global [%0], [%1], 16;" :: "r"(s), "l"(g));
}
__device__ __forceinline__ void ldsm_x4(uint32_t& r0, uint32_t& r1, uint32_t& r2, uint32_t& r3,
                                        uint32_t addr) {
    asm volatile("ldmatrix.sync.aligned.m8n8.x4.shared.b16 {%0,%1,%2,%3}, [%4];"
                 : "=r"(r0), "=r"(r1), "=r"(r2), "=r"(r3) : "r"(addr));
}
__device__ __forceinline__ void mma16816(float* c, uint32_t a0, uint32_t a1, uint32_t a2,
                                         uint32_t a3, uint32_t b0, uint32_t b1) {
    asm volatile(
        "mma.sync.aligned.m16n8k16.row.col.f32.bf16.bf16.f32 "
        "{%0,%1,%2,%3}, {%4,%5,%6,%7}, {%8,%9}, {%0,%1,%2,%3};"
        : "+f"(c[0]), "+f"(c[1]), "+f"(c[2]), "+f"(c[3])
        : "r"(a0), "r"(a1), "r"(a2), "r"(a3), "r"(b0), "r"(b1));
}

// ---- K0: transpose weights ----
__global__ void transpose_w(const float* __restrict__ Wa, const float* __restrict__ Wp) {
    int k = blockIdx.x & (DD - 1);
    const float* src = (blockIdx.x < DD) ? Wa : Wp;
    float* dst = (blockIdx.x < DD) ? g_Wt_att : g_Wt_proj;
    dst[k * DD + threadIdx.x] = src[threadIdx.x * DD + k];
}

// ---- K1a: inc -> incT bf16 tiles [e=128 rows][m=64 cols], SW128-swizzled in gmem ----
__global__ __launch_bounds__(256) void conv_inc(const float* __restrict__ inc) {
    __shared__ float s[64 * 129];
    int tid = threadIdx.x;
    int kc = blockIdx.x, et = blockIdx.y, b = blockIdx.z;
    const float* src = inc + ((size_t)b * MM + kc * 64) * EE + et * 128;
#pragma unroll
    for (int it = 0; it < 8; it++) {
        int idx = tid + it * 256;
        int row = idx >> 5, c4 = idx & 31;
        float4 v = *(const float4*)(src + (size_t)row * EE + c4 * 4);
        s[row * 129 + c4 * 4 + 0] = v.x; s[row * 129 + c4 * 4 + 1] = v.y;
        s[row * 129 + c4 * 4 + 2] = v.z; s[row * 129 + c4 * 4 + 3] = v.w;
    }
    __syncthreads();
    char* dst = g_A + ((size_t)(b * 8 + et) * NKC + kc) * A_TILE_BYTES;
#pragma unroll
    for (int it = 0; it < 4; it++) {
        int cid = tid + it * 256;
        int erow = cid >> 3, m16 = cid & 7;
        uint32_t p[4];
#pragma unroll
        for (int q = 0; q < 4; q++) {
            float xl = s[(m16 * 8 + 2 * q) * 129 + erow];
            float xh = s[(m16 * 8 + 2 * q + 1) * 129 + erow];
            asm("cvt.rn.bf16x2.f32 %0, %1, %2;" : "=r"(p[q]) : "f"(xh), "f"(xl));
        }
        uint32_t off = SWZ128((uint32_t)(erow * 128 + m16 * 16));
        *(uint4*)(dst + off) = make_uint4(p[0], p[1], p[2], p[3]);
    }
}

// ---- K1b: feats -> 3 bf16 splits (hi/lo/lolo), [d=128 rows][m=64 cols], swizzled ----
__global__ __launch_bounds__(256) void conv_feats(const float* __restrict__ feats) {
    __shared__ float s[64 * 129];
    int tid = threadIdx.x;
    int kc = blockIdx.x, b = blockIdx.y;
    const float* src = feats + ((size_t)b * MM + kc * 64) * DD;
#pragma unroll
    for (int it = 0; it < 8; it++) {
        int idx = tid + it * 256;
        int row = idx >> 5, c4 = idx & 31;
        float4 v = *(const float4*)(src + (size_t)row * DD + c4 * 4);
        s[row * 129 + c4 * 4 + 0] = v.x; s[row * 129 + c4 * 4 + 1] = v.y;
        s[row * 129 + c4 * 4 + 2] = v.z; s[row * 129 + c4 * 4 + 3] = v.w;
    }
    __syncthreads();
    char* dst = g_Bs + ((size_t)(b * NKC + kc) * 3) * B_TILE_BYTES;
#pragma unroll
    for (int it = 0; it < 4; it++) {
        int cid = tid + it * 256;
        int drow = cid >> 3, m16 = cid & 7;
        uint32_t ph[4], pl[4], pll[4];
#pragma unroll
        for (int q = 0; q < 4; q++) {
            float h[2], l[2], ll[2];
#pragma unroll
            for (int u = 0; u < 2; u++) {
                float x = s[(m16 * 8 + 2 * q + u) * 129 + drow];
                h[u] = __bfloat162float(__float2bfloat16_rn(x));
                float r = x - h[u];
                l[u] = __bfloat162float(__float2bfloat16_rn(r));
                ll[u] = r - l[u];
            }
            asm("cvt.rn.bf16x2.f32 %0, %1, %2;" : "=r"(ph[q])  : "f"(h[1]),  "f"(h[0]));
            asm("cvt.rn.bf16x2.f32 %0, %1, %2;" : "=r"(pl[q])  : "f"(l[1]),  "f"(l[0]));
            asm("cvt.rn.bf16x2.f32 %0, %1, %2;" : "=r"(pll[q]) : "f"(ll[1]), "f"(ll[0]));
        }
        uint32_t off = SWZ128((uint32_t)(drow * 128 + m16 * 16));
        *(uint4*)(dst + off)                    = make_uint4(ph[0], ph[1], ph[2], ph[3]);
        *(uint4*)(dst + B_TILE_BYTES + off)     = make_uint4(pl[0], pl[1], pl[2], pl[3]);
        *(uint4*)(dst + 2 * B_TILE_BYTES + off) = make_uint4(pll[0], pll[1], pll[2], pll[3]);
    }
}

// ---- K2: ldmatrix + mma.sync bf16 GEMM: aggp[kh][b][e][d] = sum_m inc*feat (m-half) ----
// 256 thr = 8 warps (2 e x 4 d); warp tile 64e x 32d; acc fp32.
__global__ __launch_bounds__(256, 1) void mma_agg_kernel() {
    extern __shared__ char dsm[];
    uint32_t base = smem_u32(dsm);   // 1024-aligned by attribute (dynamic smem is 16B.. force align below)

    int tid = threadIdx.x, lane = tid & 31, wid = tid >> 5;
    int warp_e = wid & 1, warp_d = wid >> 1;
    int et = blockIdx.x, b = blockIdx.y, kh = blockIdx.z;

    const char* gA = g_A + ((size_t)(b * 8 + et) * NKC) * A_TILE_BYTES;
    const char* gB = g_Bs + ((size_t)b * NKC * 3) * B_TILE_BYTES;
    int kc0 = kh * NCHUNK;

    auto stage_copy = [&](uint32_t sdst, int kc) {
        const char* a = gA + (size_t)kc * A_TILE_BYTES;
        const char* bb = gB + (size_t)kc * 3 * B_TILE_BYTES;
#pragma unroll
        for (int k = 0; k < 4; k++) {
            int off = (tid + k * 256) * 16;
            cpasync16(sdst + off, a + off);
        }
#pragma unroll
        for (int k = 0; k < 12; k++) {
            int off = (tid + k * 256) * 16;
            cpasync16(sdst + A_TILE_BYTES + off, bb + off);
        }
        asm volatile("cp.async.commit_group;" ::: "memory");
    };

    float acc[4][4][4];
#pragma unroll
    for (int i = 0; i < 4; i++)
#pragma unroll
        for (int j = 0; j < 4; j++)
#pragma unroll
            for (int c = 0; c < 4; c++) acc[i][j][c] = 0.f;

    // canonical ldmatrix lane->address pieces
    int a_row = warp_e * 64 + (lane & 15);                     // + ei*16
    int a_kb  = (lane >> 4) << 4;                              // + t*32
    int b_row = warp_d * 32 + (lane & 7) + ((lane >> 4) << 3); // + j*16
    int b_kb  = (lane & 8) * 2;                                // + t*32

    stage_copy(base, kc0);
    stage_copy(base + STAGE_BYTES, kc0 + 1);

    for (int i = 0; i < NCHUNK; i++) {
        uint32_t sb = base + (i & 1) * STAGE_BYTES;
        if (i + 1 < NCHUNK) { asm volatile("cp.async.wait_group 1;" ::: "memory"); }
        else                { asm volatile("cp.async.wait_group 0;" ::: "memory"); }
        __syncthreads();

        uint32_t sA = sb, sB = sb + A_TILE_BYTES;
#pragma unroll
        for (int t = 0; t < 4; t++) {
            uint32_t a[4][4];
#pragma unroll
            for (int ei = 0; ei < 4; ei++) {
                uint32_t off = (uint32_t)((a_row + ei * 16) * 128 + a_kb + t * 32);
                ldsm_x4(a[ei][0], a[ei][1], a[ei][2], a[ei][3], sA + SWZ128(off));
            }
#pragma unroll
            for (int s = 0; s < 3; s++) {
#pragma unroll
                for (int j = 0; j < 2; j++) {
                    uint32_t b0, b1, b2, b3;
                    uint32_t off = (uint32_t)((b_row + j * 16) * 128 + b_kb + t * 32);
                    ldsm_x4(b0, b1, b2, b3, sB + s * B_TILE_BYTES + SWZ128(off));
#pragma unroll
                    for (int ei = 0; ei < 4; ei++) {
                        mma16816(acc[ei][j * 2 + 0], a[ei][0], a[ei][1], a[ei][2], a[ei][3], b0, b1);
                        mma16816(acc[ei][j * 2 + 1], a[ei][0], a[ei][1], a[ei][2], a[ei][3], b2, b3);
                    }
                }
            }
        }
        __syncthreads();
        if (i + 2 < NCHUNK) stage_copy(sb, kc0 + i + 2);
    }

    // epilogue: c-fragment rows gr/gr+8, cols 2*(lane&3)
    float* gout = g_aggp + (((size_t)kh * BB + b) * EE + et * 128) * DD;
    int gr = lane >> 2, gc = (lane & 3) * 2;
#pragma unroll
    for (int ei = 0; ei < 4; ei++) {
#pragma unroll
        for (int jj = 0; jj < 4; jj++) {
            int e_ = warp_e * 64 + ei * 16 + gr;
            int d_ = warp_d * 32 + jj * 8 + gc;
            *(float2*)(gout + (size_t)e_ * DD + d_) = make_float2(acc[ei][jj][0], acc[ei][jj][1]);
            *(float2*)(gout + (size_t)(e_ + 8) * DD + d_) = make_float2(acc[ei][jj][2], acc[ei][jj][3]);
        }
    }
}

// ---- K3: combine split-K ----
__global__ __launch_bounds__(256) void combine_agg() {
    size_t i = ((size_t)blockIdx.x * 256 + threadIdx.x) * 4;
    float4 a = *(const float4*)(g_aggp + i);
    float4 c = *(const float4*)(g_aggp + (size_t)BB * EE * DD + i);
    a.x += c.x; a.y += c.y; a.z += c.z; a.w += c.w;
    *(float4*)(g_agg + i) = a;
}

// ---- rowgemm on agg: PHASE0 -> esc (Wt_att), PHASE1 -> edgefeat (Wt_proj) + att dots ----
template <int PHASE>
__global__ __launch_bounds__(256) void rowgemm(const float* __restrict__ attw) {
    __shared__ float WtS[32 * 128];
    __shared__ float fsh[64 * 33];
    const float* __restrict__ X = g_agg;
    const float* __restrict__ Wt = (PHASE == 0) ? g_Wt_att : g_Wt_proj;
    float* __restrict__ out = (PHASE == 0) ? g_esc : g_edgefeat;

    int tid = threadIdx.x;
    int tx = tid & 31, ty = tid >> 5;
    int row0 = blockIdx.x * 64;

    float acc[8][4];
#pragma unroll
    for (int i = 0; i < 8; i++)
#pragma unroll
        for (int c = 0; c < 4; c++) acc[i][c] = 0.f;

    for (int kc = 0; kc < DD; kc += 32) {
#pragma unroll
        for (int i = 0; i < 4; i++) {
            int slot = tid + i * 256;
            int k = slot >> 5, j4 = slot & 31;
            *reinterpret_cast<float4*>(&WtS[k * 128 + j4 * 4]) =
                *reinterpret_cast<const float4*>(&Wt[(kc + k) * DD + j4 * 4]);
        }
#pragma unroll
        for (int i = 0; i < 2; i++) {
            int slot = tid + i * 256;
            int r = slot >> 3, kq = slot & 7;
            float4 v = *reinterpret_cast<const float4*>(&X[(size_t)(row0 + r) * DD + kc + kq * 4]);
            fsh[r * 33 + kq * 4 + 0] = v.x; fsh[r * 33 + kq * 4 + 1] = v.y;
            fsh[r * 33 + kq * 4 + 2] = v.z; fsh[r * 33 + kq * 4 + 3] = v.w;
        }
        __syncthreads();
#pragma unroll
        for (int k = 0; k < 32; k++) {
            float4 w4 = *reinterpret_cast<const float4*>(&WtS[k * 128 + tx * 4]);
#pragma unroll
            for (int i = 0; i < 8; i++) {
                float f = fsh[(ty * 8 + i) * 33 + k];
                acc[i][0] = fmaf(f, w4.x, acc[i][0]);
                acc[i][1] = fmaf(f, w4.y, acc[i][1]);
                acc[i][2] = fmaf(f, w4.z, acc[i][2]);
                acc[i][3] = fmaf(f, w4.w, acc[i][3]);
            }
        }
        __syncthreads();
    }

    float4 aw = make_float4(0.f, 0.f, 0.f, 0.f);
    if (PHASE == 1) aw = *reinterpret_cast<const float4*>(&attw[tx * 4]);

#pragma unroll
    for (int i = 0; i < 8; i++) {
        int r = row0 + ty * 8 + i;
        float4 v = make_float4(acc[i][0], acc[i][1], acc[i][2], acc[i][3]);
        *reinterpret_cast<float4*>(&out[(size_t)r * DD + tx * 4]) = v;
        if (PHASE == 1) {
            float p = v.x * aw.x + v.y * aw.y + v.z * aw.z + v.w * aw.w;
#pragma unroll
            for (int off = 16; off > 0; off >>= 1)
                p += __shfl_xor_sync(0xffffffffu, p, off);
            if (tx == 0) g_att[r] = p;
        }
    }
}

// ---- K4: softmax denom over e (two-phase; no max-sub: |esc| < ~45 << 88) ----
__global__ __launch_bounds__(256) void colsum_part() {
    int ch = blockIdx.x, b = blockIdx.y;
    int d = threadIdx.x & 127, half = threadIdx.x >> 7;
    __shared__ float red[256];
    const float* __restrict__ esc = g_esc + ((size_t)b * EE + ch * 128 + half * 64) * DD;
    float s = 0.f;
#pragma unroll 4
    for (int j = 0; j < 64; j++) s += __expf(esc[(size_t)j * DD + d]);
    red[threadIdx.x] = s;
    __syncthreads();
    if (half == 0) g_colpart[(b * 8 + ch) * DD + d] = red[d] + red[d + 128];
}
__global__ __launch_bounds__(128) void colsum_fin() {
    int b = blockIdx.x, d = threadIdx.x;
    float t = 0.f;
#pragma unroll
    for (int ch = 0; ch < 8; ch++) t += g_colpart[(b * 8 + ch) * DD + d];
    g_colsum[b * DD + d] = t;
}

// ---- K5: agg <- agg * exp(esc)/colsum ----
__global__ __launch_bounds__(256) void attn_mul() {
    int idx4 = blockIdx.x * 256 + threadIdx.x;
    size_t basei = (size_t)idx4 * 4;
    int b = (int)(basei >> 17);
    int d = (int)(basei & 127);
    float4 a = *reinterpret_cast<const float4*>(&g_agg[basei]);
    float4 s = *reinterpret_cast<const float4*>(&g_esc[basei]);
    float4 cs = *reinterpret_cast<const float4*>(&g_colsum[b * DD + d]);
    a.x = a.x * __expf(s.x) / cs.x;
    a.y = a.y * __expf(s.y) / cs.y;
    a.z = a.z * __expf(s.z) / cs.z;
    a.w = a.w * __expf(s.w) / cs.w;
    *reinterpret_cast<float4*>(&g_agg[basei]) = a;
}

// ---- K6: edge softmax pooling ----
__global__ __launch_bounds__(256) void pool_kernel() {
    int b = blockIdx.x;
    int tid = threadIdx.x;
    __shared__ float ew[EE];
    __shared__ float red[256];
    __shared__ float part[256];

    float s = 0.f;
    for (int e = tid; e < EE; e += 256) {
        float w = __expf(g_att[b * EE + e]);
        ew[e] = w;
        s += w;
    }
    red[tid] = s;
    __syncthreads();
#pragma unroll
    for (int st = 128; st > 0; st >>= 1) {
        if (tid < st) red[tid] += red[tid + st];
        __syncthreads();
    }
    float S = red[0];

    int d = tid & 127, h = tid >> 7;
    const float* __restrict__ ef = g_edgefeat + (size_t)b * EE * DD;
    float acc = 0.f;
    for (int e = h * 512; e < h * 512 + 512; e++)
        acc = fmaf(ef[(size_t)e * DD + d], ew[e], acc);
    part[tid] = acc;
    __syncthreads();
    if (tid < 128) g_pooled[b * DD + tid] = (part[tid] + part[tid + 128]) / S;
}

// ---- K7: head ----
__global__ __launch_bounds__(128) void head_kernel(const float* __restrict__ ec_proj_w,
                                                   const float* __restrict__ ec_proj_b,
                                                   const float* __restrict__ fc_w,
                                                   const float* __restrict__ fc_b,
                                                   float* __restrict__ out) {
    int b = blockIdx.x;
    int d = threadIdx.x;
    __shared__ float p[DD];
    __shared__ float o[DD];
    p[d] = g_pooled[b * DD + d];
    __syncthreads();
    float acc = ec_proj_b[d];
#pragma unroll 4
    for (int k = 0; k < DD; k++) acc = fmaf(p[k], ec_proj_w[d * DD + k], acc);
    o[d] = acc;
    __syncthreads();
    if (d < NCAT) {
        float l = fc_b[d];
#pragma unroll 4
        for (int k = 0; k < DD; k++) l = fmaf(o[k], fc_w[d * DD + k], l);
        out[b * NCAT + d] = l;
    }
}

// ---- launch ----
extern "C" void kernel_launch(void* const* d_in, const int* in_sizes, int n_in,
                              void* d_out, int out_size) {
    const float* node_feats = (const float*)d_in[0];
    const float* inc_mat    = (const float*)d_in[1];
    const float* W_att      = (const float*)d_in[2];
    const float* W_proj     = (const float*)d_in[3];
    const float* ec_att_w   = (const float*)d_in[4];
    const float* ec_proj_w  = (const float*)d_in[5];
    const float* ec_proj_b  = (const float*)d_in[6];
    const float* fc_w       = (const float*)d_in[7];
    const float* fc_b       = (const float*)d_in[8];
    float* out = (float*)d_out;

    cudaFuncSetAttribute(mma_agg_kernel, cudaFuncAttributeMaxDynamicSharedMemorySize, DYN_SMEM);

    transpose_w<<<2 * DD, DD>>>(W_att, W_proj);
    conv_inc<<<dim3(NKC, 8, BB), 256>>>(inc_mat);
    conv_feats<<<dim3(NKC, BB), 256>>>(node_feats);
    mma_agg_kernel<<<dim3(8, BB, NKH), 256, DYN_SMEM>>>();
    combine_agg<<<(BB * EE * DD) / 1024, 256>>>();
    rowgemm<0><<<(BB * EE) / 64, 256>>>(nullptr);            // esc = agg @ W_att^T
    colsum_part<<<dim3(8, BB), 256>>>();
    colsum_fin<<<BB, 128>>>();
    attn_mul<<<(BB * EE * DD) / 1024, 256>>>();              // agg *= attn
    rowgemm<1><<<(BB * EE) / 64, 256>>>(ec_att_w);           // edgefeat + att dots
    pool_kernel<<<BB, 256>>>();
    head_kernel<<<BB, DD>>>(ec_proj_w, ec_proj_b, fc_w, fc_b, out);
}

// round 10
// speedup vs baseline: 3.9280x; 1.2459x over previous
#include <cuda_runtime.h>
#include <cuda_bf16.h>
#include <cstdint>

#define BB 8
#define MM 4096
#define EE 1024
#define DD 128
#define NCAT 64

#define KCH 64
#define NKC (MM / KCH)          // 64
#define NKH 2
#define NCHUNK (NKC / NKH)      // 32
#define NSPLIT 2                // bf16 splits of feats (hi+lo)
#define A_TILE_BYTES (128 * KCH * 2)                         // 16384
#define B_TILE_BYTES (DD * KCH * 2)                          // 16384
#define STAGE_BYTES (A_TILE_BYTES + NSPLIT * B_TILE_BYTES)   // 49152
#define DYN_SMEM (3 * STAGE_BYTES)                           // 147456

__device__ __align__(128) char  g_A[(size_t)BB * 8 * NKC * A_TILE_BYTES];
__device__ __align__(128) char  g_Bs[(size_t)BB * NKC * NSPLIT * B_TILE_BYTES];
__device__ __align__(128) float g_aggp[NKH * BB * EE * DD];   // split-K halves
__device__ float g_Wt_att[DD * DD];
__device__ float g_Wt_proj[DD * DD];
__device__ float g_esc[BB * EE * DD];        // holds w = exp(edge_scores)
__device__ float g_edgefeat[BB * EE * DD];
__device__ float g_colpart[128 * DD];        // per-rowgemm0-block column partials
__device__ float g_colsum[BB * DD];          // INVERSE softmax denominators
__device__ float g_att[BB * EE];             // exp(edge pooling logits)
__device__ float g_poolpart[BB * 8 * DD];
__device__ float g_poolden[BB * 8];

__device__ __forceinline__ uint32_t smem_u32(const void* p) {
    uint32_t a;
    asm("{ .reg .u64 t; cvta.to.shared.u64 t, %1; cvt.u32.u64 %0, t; }" : "=r"(a) : "l"(p));
    return a;
}
#define SWZ128(off) ((off) ^ (((off) >> 3) & 0x70))

__device__ __forceinline__ void cpasync16(uint32_t s, const void* g) {
    asm volatile("cp.async.cg.shared.global [%0], [%1], 16;" :: "r"(s), "l"(g));
}
__device__ __forceinline__ void ldsm_x4(uint32_t& r0, uint32_t& r1, uint32_t& r2, uint32_t& r3,
                                        uint32_t addr) {
    asm volatile("ldmatrix.sync.aligned.m8n8.x4.shared.b16 {%0,%1,%2,%3}, [%4];"
                 : "=r"(r0), "=r"(r1), "=r"(r2), "=r"(r3) : "r"(addr));
}
__device__ __forceinline__ void mma16816(float* c, uint32_t a0, uint32_t a1, uint32_t a2,
                                         uint32_t a3, uint32_t b0, uint32_t b1) {
    asm volatile(
        "mma.sync.aligned.m16n8k16.row.col.f32.bf16.bf16.f32 "
        "{%0,%1,%2,%3}, {%4,%5,%6,%7}, {%8,%9}, {%0,%1,%2,%3};"
        : "+f"(c[0]), "+f"(c[1]), "+f"(c[2]), "+f"(c[3])
        : "r"(a0), "r"(a1), "r"(a2), "r"(a3), "r"(b0), "r"(b1));
}

// ---- K0: transpose weights ----
__global__ void transpose_w(const float* __restrict__ Wa, const float* __restrict__ Wp) {
    int k = blockIdx.x & (DD - 1);
    const float* src = (blockIdx.x < DD) ? Wa : Wp;
    float* dst = (blockIdx.x < DD) ? g_Wt_att : g_Wt_proj;
    dst[k * DD + threadIdx.x] = src[threadIdx.x * DD + k];
}

// ---- K1a: inc -> incT bf16 tiles [e=128 rows][m=64 cols], SW128-swizzled in gmem ----
__global__ __launch_bounds__(256) void conv_inc(const float* __restrict__ inc) {
    __shared__ float s[64 * 129];
    int tid = threadIdx.x;
    int kc = blockIdx.x, et = blockIdx.y, b = blockIdx.z;
    const float* src = inc + ((size_t)b * MM + kc * 64) * EE + et * 128;
#pragma unroll
    for (int it = 0; it < 8; it++) {
        int idx = tid + it * 256;
        int row = idx >> 5, c4 = idx & 31;
        float4 v = *(const float4*)(src + (size_t)row * EE + c4 * 4);
        s[row * 129 + c4 * 4 + 0] = v.x; s[row * 129 + c4 * 4 + 1] = v.y;
        s[row * 129 + c4 * 4 + 2] = v.z; s[row * 129 + c4 * 4 + 3] = v.w;
    }
    __syncthreads();
    char* dst = g_A + ((size_t)(b * 8 + et) * NKC + kc) * A_TILE_BYTES;
#pragma unroll
    for (int it = 0; it < 4; it++) {
        int cid = tid + it * 256;
        int erow = cid >> 3, m16 = cid & 7;
        uint32_t p[4];
#pragma unroll
        for (int q = 0; q < 4; q++) {
            float xl = s[(m16 * 8 + 2 * q) * 129 + erow];
            float xh = s[(m16 * 8 + 2 * q + 1) * 129 + erow];
            asm("cvt.rn.bf16x2.f32 %0, %1, %2;" : "=r"(p[q]) : "f"(xh), "f"(xl));
        }
        uint32_t off = SWZ128((uint32_t)(erow * 128 + m16 * 16));
        *(uint4*)(dst + off) = make_uint4(p[0], p[1], p[2], p[3]);
    }
}

// ---- K1b: feats -> 2 bf16 splits (hi/lo), [d=128 rows][m=64 cols], swizzled ----
__global__ __launch_bounds__(256) void conv_feats(const float* __restrict__ feats) {
    __shared__ float s[64 * 129];
    int tid = threadIdx.x;
    int kc = blockIdx.x, b = blockIdx.y;
    const float* src = feats + ((size_t)b * MM + kc * 64) * DD;
#pragma unroll
    for (int it = 0; it < 8; it++) {
        int idx = tid + it * 256;
        int row = idx >> 5, c4 = idx & 31;
        float4 v = *(const float4*)(src + (size_t)row * DD + c4 * 4);
        s[row * 129 + c4 * 4 + 0] = v.x; s[row * 129 + c4 * 4 + 1] = v.y;
        s[row * 129 + c4 * 4 + 2] = v.z; s[row * 129 + c4 * 4 + 3] = v.w;
    }
    __syncthreads();
    char* dst = g_Bs + ((size_t)(b * NKC + kc) * NSPLIT) * B_TILE_BYTES;
#pragma unroll
    for (int it = 0; it < 4; it++) {
        int cid = tid + it * 256;
        int drow = cid >> 3, m16 = cid & 7;
        uint32_t ph[4], pl[4];
#pragma unroll
        for (int q = 0; q < 4; q++) {
            float h[2], l[2];
#pragma unroll
            for (int u = 0; u < 2; u++) {
                float x = s[(m16 * 8 + 2 * q + u) * 129 + drow];
                h[u] = __bfloat162float(__float2bfloat16_rn(x));
                l[u] = x - h[u];   // exact; its bf16 rounding leaves only ~2^-18 rel residual
            }
            asm("cvt.rn.bf16x2.f32 %0, %1, %2;" : "=r"(ph[q]) : "f"(h[1]), "f"(h[0]));
            asm("cvt.rn.bf16x2.f32 %0, %1, %2;" : "=r"(pl[q]) : "f"(l[1]), "f"(l[0]));
        }
        uint32_t off = SWZ128((uint32_t)(drow * 128 + m16 * 16));
        *(uint4*)(dst + off)                = make_uint4(ph[0], ph[1], ph[2], ph[3]);
        *(uint4*)(dst + B_TILE_BYTES + off) = make_uint4(pl[0], pl[1], pl[2], pl[3]);
    }
}

// ---- K2: ldmatrix + mma.sync bf16 GEMM, 3-stage cp.async pipeline ----
// 256 thr = 8 warps (2 e x 4 d); warp tile 64e x 32d; fp32 acc. HMMA-rate bound.
__global__ __launch_bounds__(256, 1) void mma_agg_kernel() {
    extern __shared__ char dsm[];
    uint32_t base = smem_u32(dsm);

    int tid = threadIdx.x, lane = tid & 31, wid = tid >> 5;
    int warp_e = wid & 1, warp_d = wid >> 1;
    int et = blockIdx.x, b = blockIdx.y, kh = blockIdx.z;

    const char* gA = g_A + ((size_t)(b * 8 + et) * NKC) * A_TILE_BYTES;
    const char* gB = g_Bs + ((size_t)b * NKC * NSPLIT) * B_TILE_BYTES;
    int kc0 = kh * NCHUNK;

    auto stage_copy = [&](uint32_t sdst, int kc) {
        const char* a = gA + (size_t)kc * A_TILE_BYTES;
        const char* bb = gB + (size_t)kc * NSPLIT * B_TILE_BYTES;
#pragma unroll
        for (int k = 0; k < 4; k++) {
            int off = (tid + k * 256) * 16;
            cpasync16(sdst + off, a + off);
        }
#pragma unroll
        for (int k = 0; k < 8; k++) {
            int off = (tid + k * 256) * 16;
            cpasync16(sdst + A_TILE_BYTES + off, bb + off);
        }
        asm volatile("cp.async.commit_group;" ::: "memory");
    };

    float acc[4][4][4];
#pragma unroll
    for (int i = 0; i < 4; i++)
#pragma unroll
        for (int j = 0; j < 4; j++)
#pragma unroll
            for (int c = 0; c < 4; c++) acc[i][j][c] = 0.f;

    int a_row = warp_e * 64 + (lane & 15);
    int a_kb  = (lane >> 4) << 4;
    int b_row = warp_d * 32 + (lane & 7) + ((lane >> 4) << 3);
    int b_kb  = (lane & 8) * 2;

    stage_copy(base, kc0);
    stage_copy(base + STAGE_BYTES, kc0 + 1);
    stage_copy(base + 2 * STAGE_BYTES, kc0 + 2);

    for (int i = 0; i < NCHUNK; i++) {
        uint32_t sb = base + (i % 3) * STAGE_BYTES;
        if (i < NCHUNK - 2)       { asm volatile("cp.async.wait_group 2;" ::: "memory"); }
        else if (i == NCHUNK - 2) { asm volatile("cp.async.wait_group 1;" ::: "memory"); }
        else                      { asm volatile("cp.async.wait_group 0;" ::: "memory"); }
        __syncthreads();

        uint32_t sA = sb, sB = sb + A_TILE_BYTES;
#pragma unroll
        for (int t = 0; t < 4; t++) {
            uint32_t a[4][4];
#pragma unroll
            for (int ei = 0; ei < 4; ei++) {
                uint32_t off = (uint32_t)((a_row + ei * 16) * 128 + a_kb + t * 32);
                ldsm_x4(a[ei][0], a[ei][1], a[ei][2], a[ei][3], sA + SWZ128(off));
            }
#pragma unroll
            for (int s = 0; s < NSPLIT; s++) {
#pragma unroll
                for (int j = 0; j < 2; j++) {
                    uint32_t b0, b1, b2, b3;
                    uint32_t off = (uint32_t)((b_row + j * 16) * 128 + b_kb + t * 32);
                    ldsm_x4(b0, b1, b2, b3, sB + s * B_TILE_BYTES + SWZ128(off));
#pragma unroll
                    for (int ei = 0; ei < 4; ei++) {
                        mma16816(acc[ei][j * 2 + 0], a[ei][0], a[ei][1], a[ei][2], a[ei][3], b0, b1);
                        mma16816(acc[ei][j * 2 + 1], a[ei][0], a[ei][1], a[ei][2], a[ei][3], b2, b3);
                    }
                }
            }
        }
        __syncthreads();
        if (i + 3 < NCHUNK) stage_copy(sb, kc0 + i + 3);
    }

    float* gout = g_aggp + (((size_t)kh * BB + b) * EE + et * 128) * DD;
    int gr = lane >> 2, gc = (lane & 3) * 2;
#pragma unroll
    for (int ei = 0; ei < 4; ei++) {
#pragma unroll
        for (int jj = 0; jj < 4; jj++) {
            int e_ = warp_e * 64 + ei * 16 + gr;
            int d_ = warp_d * 32 + jj * 8 + gc;
            *(float2*)(gout + (size_t)e_ * DD + d_) = make_float2(acc[ei][jj][0], acc[ei][jj][1]);
            *(float2*)(gout + (size_t)(e_ + 8) * DD + d_) = make_float2(acc[ei][jj][2], acc[ei][jj][3]);
        }
    }
}

// ---- rowgemm on agg = aggp0+aggp1 (summed inline; no combine pass)
// PHASE 0: esc GEMM (Wt_att) -> stores w=exp(esc) + per-block column partials
// PHASE 1: edgefeat GEMM on (agg * w * invcolsum) (Wt_proj) + exp(att)-dot epilogue
template <int PHASE>
__global__ __launch_bounds__(256) void rowgemm(const float* __restrict__ attw) {
    __shared__ float WtS[32 * 128];
    __shared__ float fsh[64 * 33];
    const float* __restrict__ X0 = g_aggp;
    const float* __restrict__ X1 = g_aggp + (size_t)BB * EE * DD;
    const float* __restrict__ Wt = (PHASE == 0) ? g_Wt_att : g_Wt_proj;
    float* __restrict__ out = (PHASE == 0) ? g_esc : g_edgefeat;

    int tid = threadIdx.x;
    int tx = tid & 31, ty = tid >> 5;
    int row0 = blockIdx.x * 64;

    float acc[8][4];
#pragma unroll
    for (int i = 0; i < 8; i++)
#pragma unroll
        for (int c = 0; c < 4; c++) acc[i][c] = 0.f;

    for (int kc = 0; kc < DD; kc += 32) {
#pragma unroll
        for (int i = 0; i < 4; i++) {
            int slot = tid + i * 256;
            int k = slot >> 5, j4 = slot & 31;
            *reinterpret_cast<float4*>(&WtS[k * 128 + j4 * 4]) =
                *reinterpret_cast<const float4*>(&Wt[(kc + k) * DD + j4 * 4]);
        }
#pragma unroll
        for (int i = 0; i < 2; i++) {
            int slot = tid + i * 256;
            int r = slot >> 3, kq = slot & 7;
            size_t idx = (size_t)(row0 + r) * DD + kc + kq * 4;
            float4 v0 = *reinterpret_cast<const float4*>(&X0[idx]);
            float4 v1 = *reinterpret_cast<const float4*>(&X1[idx]);
            float fx = v0.x + v1.x, fy = v0.y + v1.y, fz = v0.z + v1.z, fw = v0.w + v1.w;
            if (PHASE == 1) {
                int bb = (row0 + r) >> 10;
                float4 w = *reinterpret_cast<const float4*>(&g_esc[idx]);
                float4 ic = *reinterpret_cast<const float4*>(&g_colsum[bb * DD + kc + kq * 4]);
                fx *= w.x * ic.x; fy *= w.y * ic.y; fz *= w.z * ic.z; fw *= w.w * ic.w;
            }
            fsh[r * 33 + kq * 4 + 0] = fx; fsh[r * 33 + kq * 4 + 1] = fy;
            fsh[r * 33 + kq * 4 + 2] = fz; fsh[r * 33 + kq * 4 + 3] = fw;
        }
        __syncthreads();
#pragma unroll
        for (int k = 0; k < 32; k++) {
            float4 w4 = *reinterpret_cast<const float4*>(&WtS[k * 128 + tx * 4]);
#pragma unroll
            for (int i = 0; i < 8; i++) {
                float f = fsh[(ty * 8 + i) * 33 + k];
                acc[i][0] = fmaf(f, w4.x, acc[i][0]);
                acc[i][1] = fmaf(f, w4.y, acc[i][1]);
                acc[i][2] = fmaf(f, w4.z, acc[i][2]);
                acc[i][3] = fmaf(f, w4.w, acc[i][3]);
            }
        }
        __syncthreads();
    }

    if (PHASE == 0) {
        // exp in-register (overlaps FMA pipe), store w, block-reduce column partials
        float colp[4] = {0.f, 0.f, 0.f, 0.f};
#pragma unroll
        for (int i = 0; i < 8; i++) {
            int r = row0 + ty * 8 + i;
#pragma unroll
            for (int c = 0; c < 4; c++) {
                float w = __expf(acc[i][c]);
                acc[i][c] = w;
                colp[c] += w;
            }
            *reinterpret_cast<float4*>(&out[(size_t)r * DD + tx * 4]) =
                make_float4(acc[i][0], acc[i][1], acc[i][2], acc[i][3]);
        }
        __shared__ float redc[8 * 128];
        *reinterpret_cast<float4*>(&redc[ty * 128 + tx * 4]) =
            make_float4(colp[0], colp[1], colp[2], colp[3]);
        __syncthreads();
        if (ty == 0) {
#pragma unroll
            for (int c = 0; c < 4; c++) {
                float s = 0.f;
#pragma unroll
                for (int t = 0; t < 8; t++) s += redc[t * 128 + tx * 4 + c];
                g_colpart[blockIdx.x * 128 + tx * 4 + c] = s;
            }
        }
    } else {
        float4 aw = *reinterpret_cast<const float4*>(&attw[tx * 4]);
#pragma unroll
        for (int i = 0; i < 8; i++) {
            int r = row0 + ty * 8 + i;
            float4 v = make_float4(acc[i][0], acc[i][1], acc[i][2], acc[i][3]);
            *reinterpret_cast<float4*>(&out[(size_t)r * DD + tx * 4]) = v;
            float p = v.x * aw.x + v.y * aw.y + v.z * aw.z + v.w * aw.w;
#pragma unroll
            for (int off = 16; off > 0; off >>= 1)
                p += __shfl_xor_sync(0xffffffffu, p, off);
            if (tx == 0) g_att[r] = __expf(p);   // store exp of pooling logit
        }
    }
}

// ---- K4: finish column softmax denominators -> store INVERSE ----
__global__ __launch_bounds__(128) void colsum_fin() {
    int b = blockIdx.x, d = threadIdx.x;
    float t = 0.f;
#pragma unroll
    for (int blk = 0; blk < 16; blk++) t += g_colpart[(b * 16 + blk) * 128 + d];
    g_colsum[b * DD + d] = 1.f / t;
}

// ---- K5: pooling partials: numerator[d] per (b, e-chunk) + denominator ----
__global__ __launch_bounds__(256) void pool_part() {
    int ch = blockIdx.x, b = blockIdx.y;
    int tid = threadIdx.x;
    int d = tid & 127, h = tid >> 7;
    __shared__ float part[256];
    const float* __restrict__ ef = g_edgefeat + ((size_t)b * EE + ch * 128) * DD;
    const float* __restrict__ w = g_att + b * EE + ch * 128;

    float acc = 0.f;
#pragma unroll 4
    for (int j = 0; j < 64; j++) {
        int e = h * 64 + j;
        acc = fmaf(ef[(size_t)e * DD + d], w[e], acc);
    }
    part[tid] = acc;
    __syncthreads();
    if (h == 0) g_poolpart[(b * 8 + ch) * DD + d] = part[d] + part[d + 128];
    if (tid < 32) {
        float s = w[tid] + w[tid + 32] + w[tid + 64] + w[tid + 96];
#pragma unroll
        for (int off = 16; off > 0; off >>= 1) s += __shfl_xor_sync(0xffffffffu, s, off);
        if (tid == 0) g_poolden[b * 8 + ch] = s;
    }
}

// ---- K6: pooled = numer/S; out = pooled@ec_proj^T + b; logits = out@fc^T + fc_b ----
__global__ __launch_bounds__(128) void pool_head(const float* __restrict__ ec_proj_w,
                                                 const float* __restrict__ ec_proj_b,
                                                 const float* __restrict__ fc_w,
                                                 const float* __restrict__ fc_b,
                                                 float* __restrict__ out) {
    int b = blockIdx.x, d = threadIdx.x;
    __shared__ float p[DD];
    __shared__ float o[DD];
    float n = 0.f, S = 0.f;
#pragma unroll
    for (int ch = 0; ch < 8; ch++) {
        n += g_poolpart[(b * 8 + ch) * DD + d];
        S += g_poolden[b * 8 + ch];
    }
    p[d] = n / S;
    __syncthreads();
    float acc = ec_proj_b[d];
#pragma unroll 4
    for (int k = 0; k < DD; k++) acc = fmaf(p[k], ec_proj_w[d * DD + k], acc);
    o[d] = acc;
    __syncthreads();
    if (d < NCAT) {
        float l = fc_b[d];
#pragma unroll 4
        for (int k = 0; k < DD; k++) l = fmaf(o[k], fc_w[d * DD + k], l);
        out[b * NCAT + d] = l;
    }
}

// ---- launch ----
extern "C" void kernel_launch(void* const* d_in, const int* in_sizes, int n_in,
                              void* d_out, int out_size) {
    const float* node_feats = (const float*)d_in[0];
    const float* inc_mat    = (const float*)d_in[1];
    const float* W_att      = (const float*)d_in[2];
    const float* W_proj     = (const float*)d_in[3];
    const float* ec_att_w   = (const float*)d_in[4];
    const float* ec_proj_w  = (const float*)d_in[5];
    const float* ec_proj_b  = (const float*)d_in[6];
    const float* fc_w       = (const float*)d_in[7];
    const float* fc_b       = (const float*)d_in[8];
    float* out = (float*)d_out;

    cudaFuncSetAttribute(mma_agg_kernel, cudaFuncAttributeMaxDynamicSharedMemorySize, DYN_SMEM);

    transpose_w<<<2 * DD, DD>>>(W_att, W_proj);
    conv_inc<<<dim3(NKC, 8, BB), 256>>>(inc_mat);
    conv_feats<<<dim3(NKC, BB), 256>>>(node_feats);
    mma_agg_kernel<<<dim3(8, BB, NKH), 256, DYN_SMEM>>>();
    rowgemm<0><<<(BB * EE) / 64, 256>>>(nullptr);     // w=exp(esc) + column partials
    colsum_fin<<<BB, 128>>>();                        // inverse denominators
    rowgemm<1><<<(BB * EE) / 64, 256>>>(ec_att_w);    // edgefeat + exp(att) dots
    pool_part<<<dim3(8, BB), 256>>>();
    pool_head<<<BB, 128>>>(ec_proj_w, ec_proj_b, fc_w, fc_b, out);
}

// round 11
// speedup vs baseline: 5.1683x; 1.3157x over previous
#include <cuda_runtime.h>
#include <cuda_bf16.h>
#include <cstdint>

#define BB 8
#define MM 4096
#define EE 1024
#define DD 128
#define NCAT 64

#define KCH 64
#define NKC (MM / KCH)          // 64
#define NKH 2
#define NCHUNK (NKC / NKH)      // 32
#define NSPLIT 2                // bf16 splits of feats (hi+lo)
#define A_TILE_BYTES (128 * KCH * 2)        // 16384 (bf16 A tile)
#define B_TILE_BYTES (DD * KCH * 2)         // 16384 per split
#define INC_PITCH_B 544                     // 128 floats + pad, 16B aligned, conflict-free col reads
#define INC_STAGE_B (KCH * INC_PITCH_B)     // 34816
#define STAGE_BYTES (INC_STAGE_B + NSPLIT * B_TILE_BYTES)   // 67584 (mult of 128)
#define A_OFF (3 * STAGE_BYTES)                             // 202752
#define DYN_SMEM (A_OFF + A_TILE_BYTES)                     // 219136

__device__ __align__(128) char  g_Bs[(size_t)BB * NKC * NSPLIT * B_TILE_BYTES];
__device__ __align__(128) float g_aggp[NKH * BB * EE * DD];   // split-K halves
__device__ float g_Wt_att[DD * DD];
__device__ float g_Wt_proj[DD * DD];
__device__ float g_esc[BB * EE * DD];        // holds w = exp(edge_scores)
__device__ float g_colpart[128 * DD];        // per-rowgemm0-block column partials
__device__ float g_poolpart[128 * DD];       // per-rowgemm1-block pooled numerators
__device__ float g_poolden[128];             // per-rowgemm1-block pooled denominators

__device__ __forceinline__ uint32_t smem_u32(const void* p) {
    uint32_t a;
    asm("{ .reg .u64 t; cvta.to.shared.u64 t, %1; cvt.u32.u64 %0, t; }" : "=r"(a) : "l"(p));
    return a;
}
#define SWZ128(off) ((off) ^ (((off) >> 3) & 0x70))

__device__ __forceinline__ void cpasync16(uint32_t s, const void* g) {
    asm volatile("cp.async.cg.shared.global [%0], [%1], 16;" :: "r"(s), "l"(g));
}
__device__ __forceinline__ void ldsm_x4(uint32_t& r0, uint32_t& r1, uint32_t& r2, uint32_t& r3,
                                        uint32_t addr) {
    asm volatile("ldmatrix.sync.aligned.m8n8.x4.shared.b16 {%0,%1,%2,%3}, [%4];"
                 : "=r"(r0), "=r"(r1), "=r"(r2), "=r"(r3) : "r"(addr));
}
__device__ __forceinline__ void mma16816(float* c, uint32_t a0, uint32_t a1, uint32_t a2,
                                         uint32_t a3, uint32_t b0, uint32_t b1) {
    asm volatile(
        "mma.sync.aligned.m16n8k16.row.col.f32.bf16.bf16.f32 "
        "{%0,%1,%2,%3}, {%4,%5,%6,%7}, {%8,%9}, {%0,%1,%2,%3};"
        : "+f"(c[0]), "+f"(c[1]), "+f"(c[2]), "+f"(c[3])
        : "r"(a0), "r"(a1), "r"(a2), "r"(a3), "r"(b0), "r"(b1));
}

// ---- K0: transpose weights ----
__global__ void transpose_w(const float* __restrict__ Wa, const float* __restrict__ Wp) {
    int k = blockIdx.x & (DD - 1);
    const float* src = (blockIdx.x < DD) ? Wa : Wp;
    float* dst = (blockIdx.x < DD) ? g_Wt_att : g_Wt_proj;
    dst[k * DD + threadIdx.x] = src[threadIdx.x * DD + k];
}

// ---- K1: feats -> 2 bf16 splits (hi/lo), [d=128 rows][m=64 cols], swizzled ----
__global__ __launch_bounds__(256) void conv_feats(const float* __restrict__ feats) {
    __shared__ float s[64 * 129];
    int tid = threadIdx.x;
    int kc = blockIdx.x, b = blockIdx.y;
    const float* src = feats + ((size_t)b * MM + kc * 64) * DD;
#pragma unroll
    for (int it = 0; it < 8; it++) {
        int idx = tid + it * 256;
        int row = idx >> 5, c4 = idx & 31;
        float4 v = *(const float4*)(src + (size_t)row * DD + c4 * 4);
        s[row * 129 + c4 * 4 + 0] = v.x; s[row * 129 + c4 * 4 + 1] = v.y;
        s[row * 129 + c4 * 4 + 2] = v.z; s[row * 129 + c4 * 4 + 3] = v.w;
    }
    __syncthreads();
    char* dst = g_Bs + ((size_t)(b * NKC + kc) * NSPLIT) * B_TILE_BYTES;
#pragma unroll
    for (int it = 0; it < 4; it++) {
        int cid = tid + it * 256;
        int drow = cid >> 3, m16 = cid & 7;
        uint32_t ph[4], pl[4];
#pragma unroll
        for (int q = 0; q < 4; q++) {
            float h[2], l[2];
#pragma unroll
            for (int u = 0; u < 2; u++) {
                float x = s[(m16 * 8 + 2 * q + u) * 129 + drow];
                h[u] = __bfloat162float(__float2bfloat16_rn(x));
                l[u] = x - h[u];
            }
            asm("cvt.rn.bf16x2.f32 %0, %1, %2;" : "=r"(ph[q]) : "f"(h[1]), "f"(h[0]));
            asm("cvt.rn.bf16x2.f32 %0, %1, %2;" : "=r"(pl[q]) : "f"(l[1]), "f"(l[0]));
        }
        uint32_t off = SWZ128((uint32_t)(drow * 128 + m16 * 16));
        *(uint4*)(dst + off)                = make_uint4(ph[0], ph[1], ph[2], ph[3]);
        *(uint4*)(dst + B_TILE_BYTES + off) = make_uint4(pl[0], pl[1], pl[2], pl[3]);
    }
}

// ---- K2: fused inc-convert + ldmatrix/mma.sync bf16 GEMM, 3-stage cp.async ----
// Stages hold RAW fp32 inc slab (64m x 128e) + bf16 B splits; inc is converted
// to the transposed+swizzled bf16 A tile in smem each chunk (hides under MMA).
__global__ __launch_bounds__(256, 1) void mma_agg_kernel(const float* __restrict__ inc) {
    extern __shared__ __align__(1024) char dsm[];
    uint32_t base = smem_u32(dsm);

    int tid = threadIdx.x, lane = tid & 31, wid = tid >> 5;
    int warp_e = wid & 1, warp_d = wid >> 1;
    int et = blockIdx.x, b = blockIdx.y, kh = blockIdx.z;

    const float* incB = inc + ((size_t)b * MM) * EE + et * 128;
    const char* gB = g_Bs + ((size_t)b * NKC * NSPLIT) * B_TILE_BYTES;
    int kc0 = kh * NCHUNK;

    auto stage_copy = [&](int st, int kc) {
        uint32_t sdst = base + st * STAGE_BYTES;
        const float* aF = incB + (size_t)(kc * KCH) * EE;
#pragma unroll
        for (int k = 0; k < 8; k++) {              // 64 rows x 512B fp32 inc
            int idx = tid + k * 256;
            int m = idx >> 5, c16 = idx & 31;
            cpasync16(sdst + m * INC_PITCH_B + c16 * 16, aF + (size_t)m * EE + c16 * 4);
        }
        const char* bb = gB + (size_t)kc * NSPLIT * B_TILE_BYTES;
#pragma unroll
        for (int k = 0; k < 8; k++) {              // 32KB bf16 B
            int off = (tid + k * 256) * 16;
            cpasync16(sdst + INC_STAGE_B + off, bb + off);
        }
        asm volatile("cp.async.commit_group;" ::: "memory");
    };

    float acc[4][4][4];
#pragma unroll
    for (int i = 0; i < 4; i++)
#pragma unroll
        for (int j = 0; j < 4; j++)
#pragma unroll
            for (int c = 0; c < 4; c++) acc[i][j][c] = 0.f;

    int a_row = warp_e * 64 + (lane & 15);
    int a_kb  = (lane >> 4) << 4;
    int b_row = warp_d * 32 + (lane & 7) + ((lane >> 4) << 3);
    int b_kb  = (lane & 8) * 2;

    stage_copy(0, kc0);
    stage_copy(1, kc0 + 1);
    stage_copy(2, kc0 + 2);

    for (int i = 0; i < NCHUNK; i++) {
        int st = i % 3;
        if (i < NCHUNK - 2)       { asm volatile("cp.async.wait_group 2;" ::: "memory"); }
        else if (i == NCHUNK - 2) { asm volatile("cp.async.wait_group 1;" ::: "memory"); }
        else                      { asm volatile("cp.async.wait_group 0;" ::: "memory"); }
        __syncthreads();

        // convert fp32 inc slab [m][e] -> bf16 A tile [e][m], SW128-swizzled
        {
            const float* sf = (const float*)(dsm + st * STAGE_BYTES);
#pragma unroll
            for (int rep = 0; rep < 4; rep++) {
                int cid = tid + rep * 256;
                int erow = cid & 127, mb = cid >> 7;     // 128 e-rows x 8 m-blocks
                float f[8];
#pragma unroll
                for (int q = 0; q < 8; q++)
                    f[q] = sf[(mb * 8 + q) * (INC_PITCH_B / 4) + erow];
                uint32_t p[4];
#pragma unroll
                for (int q = 0; q < 4; q++)
                    asm("cvt.rn.bf16x2.f32 %0, %1, %2;" : "=r"(p[q]) : "f"(f[2 * q + 1]), "f"(f[2 * q]));
                uint32_t off = SWZ128((uint32_t)(erow * 128 + mb * 16));
                *(uint4*)(dsm + A_OFF + off) = make_uint4(p[0], p[1], p[2], p[3]);
            }
        }
        __syncthreads();

        uint32_t sA = base + A_OFF;
        uint32_t sB = base + st * STAGE_BYTES + INC_STAGE_B;
#pragma unroll
        for (int t = 0; t < 4; t++) {
            uint32_t a[4][4];
#pragma unroll
            for (int ei = 0; ei < 4; ei++) {
                uint32_t off = (uint32_t)((a_row + ei * 16) * 128 + a_kb + t * 32);
                ldsm_x4(a[ei][0], a[ei][1], a[ei][2], a[ei][3], sA + SWZ128(off));
            }
#pragma unroll
            for (int s = 0; s < NSPLIT; s++) {
#pragma unroll
                for (int j = 0; j < 2; j++) {
                    uint32_t b0, b1, b2, b3;
                    uint32_t off = (uint32_t)((b_row + j * 16) * 128 + b_kb + t * 32);
                    ldsm_x4(b0, b1, b2, b3, sB + s * B_TILE_BYTES + SWZ128(off));
#pragma unroll
                    for (int ei = 0; ei < 4; ei++) {
                        mma16816(acc[ei][j * 2 + 0], a[ei][0], a[ei][1], a[ei][2], a[ei][3], b0, b1);
                        mma16816(acc[ei][j * 2 + 1], a[ei][0], a[ei][1], a[ei][2], a[ei][3], b2, b3);
                    }
                }
            }
        }
        __syncthreads();
        if (i + 3 < NCHUNK) stage_copy(st, kc0 + i + 3);
    }

    float* gout = g_aggp + (((size_t)kh * BB + b) * EE + et * 128) * DD;
    int gr = lane >> 2, gc = (lane & 3) * 2;
#pragma unroll
    for (int ei = 0; ei < 4; ei++) {
#pragma unroll
        for (int jj = 0; jj < 4; jj++) {
            int e_ = warp_e * 64 + ei * 16 + gr;
            int d_ = warp_d * 32 + jj * 8 + gc;
            *(float2*)(gout + (size_t)e_ * DD + d_) = make_float2(acc[ei][jj][0], acc[ei][jj][1]);
            *(float2*)(gout + (size_t)(e_ + 8) * DD + d_) = make_float2(acc[ei][jj][2], acc[ei][jj][3]);
        }
    }
}

// ---- rowgemm on agg = aggp0+aggp1 (summed inline)
// PHASE 0: esc GEMM (Wt_att) -> stores w=exp(esc) + per-block column partials
// PHASE 1: edgefeat GEMM on (agg * w * invcolsum) (Wt_proj); edgefeat stays in
//          registers; fused att-softmax pooling -> per-block numer/denom.
template <int PHASE>
__global__ __launch_bounds__(256) void rowgemm(const float* __restrict__ attw) {
    __shared__ float WtS[32 * 128];
    __shared__ float fsh[64 * 33];
    __shared__ __align__(16) float sICS[128];
    __shared__ float redc[8 * 128];
    __shared__ float sden[8];
    const float* __restrict__ X0 = g_aggp;
    const float* __restrict__ X1 = g_aggp + (size_t)BB * EE * DD;
    const float* __restrict__ Wt = (PHASE == 0) ? g_Wt_att : g_Wt_proj;

    int tid = threadIdx.x;
    int tx = tid & 31, ty = tid >> 5;
    int row0 = blockIdx.x * 64;
    int bb = row0 >> 10;

    if (PHASE == 1) {   // finish column-softmax denominators -> inverse, in smem
        if (tid < 128) {
            float t = 0.f;
#pragma unroll
            for (int blk = 0; blk < 16; blk++) t += g_colpart[(bb * 16 + blk) * 128 + tid];
            sICS[tid] = 1.f / t;
        }
        __syncthreads();
    }

    float acc[8][4];
#pragma unroll
    for (int i = 0; i < 8; i++)
#pragma unroll
        for (int c = 0; c < 4; c++) acc[i][c] = 0.f;

    for (int kc = 0; kc < DD; kc += 32) {
#pragma unroll
        for (int i = 0; i < 4; i++) {
            int slot = tid + i * 256;
            int k = slot >> 5, j4 = slot & 31;
            *reinterpret_cast<float4*>(&WtS[k * 128 + j4 * 4]) =
                *reinterpret_cast<const float4*>(&Wt[(kc + k) * DD + j4 * 4]);
        }
#pragma unroll
        for (int i = 0; i < 2; i++) {
            int slot = tid + i * 256;
            int r = slot >> 3, kq = slot & 7;
            size_t idx = (size_t)(row0 + r) * DD + kc + kq * 4;
            float4 v0 = *reinterpret_cast<const float4*>(&X0[idx]);
            float4 v1 = *reinterpret_cast<const float4*>(&X1[idx]);
            float fx = v0.x + v1.x, fy = v0.y + v1.y, fz = v0.z + v1.z, fw = v0.w + v1.w;
            if (PHASE == 1) {
                float4 w = *reinterpret_cast<const float4*>(&g_esc[idx]);
                float4 ic = *reinterpret_cast<const float4*>(&sICS[kc + kq * 4]);
                fx *= w.x * ic.x; fy *= w.y * ic.y; fz *= w.z * ic.z; fw *= w.w * ic.w;
            }
            fsh[r * 33 + kq * 4 + 0] = fx; fsh[r * 33 + kq * 4 + 1] = fy;
            fsh[r * 33 + kq * 4 + 2] = fz; fsh[r * 33 + kq * 4 + 3] = fw;
        }
        __syncthreads();
#pragma unroll
        for (int k = 0; k < 32; k++) {
            float4 w4 = *reinterpret_cast<const float4*>(&WtS[k * 128 + tx * 4]);
#pragma unroll
            for (int i = 0; i < 8; i++) {
                float f = fsh[(ty * 8 + i) * 33 + k];
                acc[i][0] = fmaf(f, w4.x, acc[i][0]);
                acc[i][1] = fmaf(f, w4.y, acc[i][1]);
                acc[i][2] = fmaf(f, w4.z, acc[i][2]);
                acc[i][3] = fmaf(f, w4.w, acc[i][3]);
            }
        }
        __syncthreads();
    }

    if (PHASE == 0) {
        float colp[4] = {0.f, 0.f, 0.f, 0.f};
#pragma unroll
        for (int i = 0; i < 8; i++) {
            int r = row0 + ty * 8 + i;
#pragma unroll
            for (int c = 0; c < 4; c++) {
                float w = __expf(acc[i][c]);
                acc[i][c] = w;
                colp[c] += w;
            }
            *reinterpret_cast<float4*>(&g_esc[(size_t)r * DD + tx * 4]) =
                make_float4(acc[i][0], acc[i][1], acc[i][2], acc[i][3]);
        }
        *reinterpret_cast<float4*>(&redc[ty * 128 + tx * 4]) =
            make_float4(colp[0], colp[1], colp[2], colp[3]);
        __syncthreads();
        if (ty == 0) {
#pragma unroll
            for (int c = 0; c < 4; c++) {
                float s = 0.f;
#pragma unroll
                for (int t = 0; t < 8; t++) s += redc[t * 128 + tx * 4 + c];
                g_colpart[blockIdx.x * 128 + tx * 4 + c] = s;
            }
        }
    } else {
        // fused attention pooling: numer_d = sum_e ef[e][d]*exp(att_e); den = sum_e exp(att_e)
        float4 aw = *reinterpret_cast<const float4*>(&attw[tx * 4]);
        float pacc[4] = {0.f, 0.f, 0.f, 0.f};
        float dacc = 0.f;
#pragma unroll
        for (int i = 0; i < 8; i++) {
            float4 v = make_float4(acc[i][0], acc[i][1], acc[i][2], acc[i][3]);
            float p = v.x * aw.x + v.y * aw.y + v.z * aw.z + v.w * aw.w;
#pragma unroll
            for (int off = 16; off > 0; off >>= 1)
                p += __shfl_xor_sync(0xffffffffu, p, off);   // all lanes get full dot
            float wv = __expf(p);
            pacc[0] = fmaf(v.x, wv, pacc[0]); pacc[1] = fmaf(v.y, wv, pacc[1]);
            pacc[2] = fmaf(v.z, wv, pacc[2]); pacc[3] = fmaf(v.w, wv, pacc[3]);
            dacc += wv;
        }
        *reinterpret_cast<float4*>(&redc[ty * 128 + tx * 4]) =
            make_float4(pacc[0], pacc[1], pacc[2], pacc[3]);
        if (tx == 0) sden[ty] = dacc;
        __syncthreads();
        if (ty == 0) {
#pragma unroll
            for (int c = 0; c < 4; c++) {
                float s = 0.f;
#pragma unroll
                for (int t = 0; t < 8; t++) s += redc[t * 128 + tx * 4 + c];
                g_poolpart[blockIdx.x * 128 + tx * 4 + c] = s;
            }
        }
        if (tid == 0) {
            float s = 0.f;
#pragma unroll
            for (int t = 0; t < 8; t++) s += sden[t];
            g_poolden[blockIdx.x] = s;
        }
    }
}

// ---- K5: pooled = numer/S; out = pooled@ec_proj^T + b; logits = out@fc^T + fc_b ----
__global__ __launch_bounds__(128) void pool_head(const float* __restrict__ ec_proj_w,
                                                 const float* __restrict__ ec_proj_b,
                                                 const float* __restrict__ fc_w,
                                                 const float* __restrict__ fc_b,
                                                 float* __restrict__ out) {
    int b = blockIdx.x, d = threadIdx.x;
    __shared__ float p[DD];
    __shared__ float o[DD];
    float n = 0.f, S = 0.f;
#pragma unroll
    for (int blk = 0; blk < 16; blk++) {
        n += g_poolpart[(b * 16 + blk) * 128 + d];
        S += g_poolden[b * 16 + blk];
    }
    p[d] = n / S;
    __syncthreads();
    float acc = ec_proj_b[d];
#pragma unroll 4
    for (int k = 0; k < DD; k++) acc = fmaf(p[k], ec_proj_w[d * DD + k], acc);
    o[d] = acc;
    __syncthreads();
    if (d < NCAT) {
        float l = fc_b[d];
#pragma unroll 4
        for (int k = 0; k < DD; k++) l = fmaf(o[k], fc_w[d * DD + k], l);
        out[b * NCAT + d] = l;
    }
}

// ---- launch ----
extern "C" void kernel_launch(void* const* d_in, const int* in_sizes, int n_in,
                              void* d_out, int out_size) {
    const float* node_feats = (const float*)d_in[0];
    const float* inc_mat    = (const float*)d_in[1];
    const float* W_att      = (const float*)d_in[2];
    const float* W_proj     = (const float*)d_in[3];
    const float* ec_att_w   = (const float*)d_in[4];
    const float* ec_proj_w  = (const float*)d_in[5];
    const float* ec_proj_b  = (const float*)d_in[6];
    const float* fc_w       = (const float*)d_in[7];
    const float* fc_b       = (const float*)d_in[8];
    float* out = (float*)d_out;

    cudaFuncSetAttribute(mma_agg_kernel, cudaFuncAttributeMaxDynamicSharedMemorySize, DYN_SMEM);

    transpose_w<<<2 * DD, DD>>>(W_att, W_proj);
    conv_feats<<<dim3(NKC, BB), 256>>>(node_feats);
    mma_agg_kernel<<<dim3(8, BB, NKH), 256, DYN_SMEM>>>(inc_mat);
    rowgemm<0><<<(BB * EE) / 64, 256>>>(nullptr);     // w=exp(esc) + column partials
    rowgemm<1><<<(BB * EE) / 64, 256>>>(ec_att_w);    // fused inv-colsum + pooling
    pool_head<<<BB, 128>>>(ec_proj_w, ec_proj_b, fc_w, fc_b, out);
}

// round 12
// speedup vs baseline: 5.2307x; 1.0121x over previous
#include <cuda_runtime.h>
#include <cuda_bf16.h>
#include <cstdint>

#define BB 8
#define MM 4096
#define EE 1024
#define DD 128
#define NCAT 64

#define KCH 64
#define NKC (MM / KCH)          // 64
#define NKH 2
#define NCHUNK (NKC / NKH)      // 32
#define NSPLIT 2                // bf16 splits of feats (hi+lo)
#define A_TILE_BYTES (128 * KCH * 2)        // 16384 (bf16 A tile)
#define B_TILE_BYTES (DD * KCH * 2)         // 16384 per split
#define INC_PITCH_B 512                     // fp32 inc row (128 floats); col reads are conflict-free
#define INC_STAGE_B (KCH * INC_PITCH_B)     // 32768
#define STAGE_BYTES (INC_STAGE_B + NSPLIT * B_TILE_BYTES)   // 65536
#define ABUF_OFF (3 * STAGE_BYTES)                          // 196608
#define DYN_SMEM (ABUF_OFF + 2 * A_TILE_BYTES)              // 229376 (<= 227KB limit)

#define RG_ROWS 32              // rowgemm rows per block
#define NRGB (BB * EE / RG_ROWS)  // 256 rowgemm blocks

__device__ __align__(128) char  g_Bs[(size_t)BB * NKC * NSPLIT * B_TILE_BYTES];
__device__ __align__(128) float g_aggp[NKH * BB * EE * DD];   // split-K halves
__device__ float g_Wt_att[DD * DD];
__device__ float g_Wt_proj[DD * DD];
__device__ float g_esc[BB * EE * DD];        // holds w = exp(edge_scores)
__device__ float g_colpart[NRGB * DD];       // per-rowgemm0-block column partials
__device__ float g_poolpart[NRGB * DD];      // per-rowgemm1-block pooled numerators
__device__ float g_poolden[NRGB];            // per-rowgemm1-block pooled denominators

__device__ __forceinline__ uint32_t smem_u32(const void* p) {
    uint32_t a;
    asm("{ .reg .u64 t; cvta.to.shared.u64 t, %1; cvt.u32.u64 %0, t; }" : "=r"(a) : "l"(p));
    return a;
}
#define SWZ128(off) ((off) ^ (((off) >> 3) & 0x70))

__device__ __forceinline__ void cpasync16(uint32_t s, const void* g) {
    asm volatile("cp.async.cg.shared.global [%0], [%1], 16;" :: "r"(s), "l"(g));
}
__device__ __forceinline__ void ldsm_x4(uint32_t& r0, uint32_t& r1, uint32_t& r2, uint32_t& r3,
                                        uint32_t addr) {
    asm volatile("ldmatrix.sync.aligned.m8n8.x4.shared.b16 {%0,%1,%2,%3}, [%4];"
                 : "=r"(r0), "=r"(r1), "=r"(r2), "=r"(r3) : "r"(addr));
}
__device__ __forceinline__ void mma16816(float* c, uint32_t a0, uint32_t a1, uint32_t a2,
                                         uint32_t a3, uint32_t b0, uint32_t b1) {
    asm volatile(
        "mma.sync.aligned.m16n8k16.row.col.f32.bf16.bf16.f32 "
        "{%0,%1,%2,%3}, {%4,%5,%6,%7}, {%8,%9}, {%0,%1,%2,%3};"
        : "+f"(c[0]), "+f"(c[1]), "+f"(c[2]), "+f"(c[3])
        : "r"(a0), "r"(a1), "r"(a2), "r"(a3), "r"(b0), "r"(b1));
}

// ---- K1: feats -> 2 bf16 splits, [d=128][m=64] swizzled; + weight transposes ----
// grid (NKC, BB+1): blocks with b==BB transpose W_att/W_proj (2 rows per block).
__global__ __launch_bounds__(256) void conv_feats(const float* __restrict__ feats,
                                                  const float* __restrict__ Wa,
                                                  const float* __restrict__ Wp) {
    int tid = threadIdx.x;
    int kc = blockIdx.x, b = blockIdx.y;
    if (b == BB) {               // transpose duty: block kc handles rows 2kc, 2kc+1
        int m = tid >> 7, j = tid & 127;
        int k = kc * 2 + m;
        g_Wt_att[k * DD + j] = Wa[j * DD + k];
        g_Wt_proj[k * DD + j] = Wp[j * DD + k];
        return;
    }
    __shared__ float s[64 * 129];
    const float* src = feats + ((size_t)b * MM + kc * 64) * DD;
#pragma unroll
    for (int it = 0; it < 8; it++) {
        int idx = tid + it * 256;
        int row = idx >> 5, c4 = idx & 31;
        float4 v = *(const float4*)(src + (size_t)row * DD + c4 * 4);
        s[row * 129 + c4 * 4 + 0] = v.x; s[row * 129 + c4 * 4 + 1] = v.y;
        s[row * 129 + c4 * 4 + 2] = v.z; s[row * 129 + c4 * 4 + 3] = v.w;
    }
    __syncthreads();
    char* dst = g_Bs + ((size_t)(b * NKC + kc) * NSPLIT) * B_TILE_BYTES;
#pragma unroll
    for (int it = 0; it < 4; it++) {
        int cid = tid + it * 256;
        int drow = cid >> 3, m16 = cid & 7;
        uint32_t ph[4], pl[4];
#pragma unroll
        for (int q = 0; q < 4; q++) {
            float h[2], l[2];
#pragma unroll
            for (int u = 0; u < 2; u++) {
                float x = s[(m16 * 8 + 2 * q + u) * 129 + drow];
                h[u] = __bfloat162float(__float2bfloat16_rn(x));
                l[u] = x - h[u];
            }
            asm("cvt.rn.bf16x2.f32 %0, %1, %2;" : "=r"(ph[q]) : "f"(h[1]), "f"(h[0]));
            asm("cvt.rn.bf16x2.f32 %0, %1, %2;" : "=r"(pl[q]) : "f"(l[1]), "f"(l[0]));
        }
        uint32_t off = SWZ128((uint32_t)(drow * 128 + m16 * 16));
        *(uint4*)(dst + off)                = make_uint4(ph[0], ph[1], ph[2], ph[3]);
        *(uint4*)(dst + B_TILE_BYTES + off) = make_uint4(pl[0], pl[1], pl[2], pl[3]);
    }
}

// ---- K2: fused inc-convert + ldmatrix/mma.sync bf16 GEMM ----
// 3 raw stages (fp32 inc + bf16 B) + DOUBLE-BUFFERED A tile: convert(i+1) is
// interleaved with mma(i) in one issue region (fills idle slots), 1 sync/chunk.
__global__ __launch_bounds__(256, 1) void mma_agg_kernel(const float* __restrict__ inc) {
    extern __shared__ __align__(1024) char dsm[];
    uint32_t base = smem_u32(dsm);

    int tid = threadIdx.x, lane = tid & 31, wid = tid >> 5;
    int warp_e = wid & 1, warp_d = wid >> 1;
    int et = blockIdx.x, b = blockIdx.y, kh = blockIdx.z;

    const float* incB = inc + ((size_t)b * MM) * EE + et * 128;
    const char* gB = g_Bs + ((size_t)b * NKC * NSPLIT) * B_TILE_BYTES;
    int kc0 = kh * NCHUNK;

    auto stage_copy = [&](int st, int kc) {
        uint32_t sdst = base + st * STAGE_BYTES;
        const float* aF = incB + (size_t)(kc * KCH) * EE;
#pragma unroll
        for (int k = 0; k < 8; k++) {              // 64 rows x 512B fp32 inc
            int idx = tid + k * 256;
            int m = idx >> 5, c16 = idx & 31;
            cpasync16(sdst + m * INC_PITCH_B + c16 * 16, aF + (size_t)m * EE + c16 * 4);
        }
        const char* bb = gB + (size_t)kc * NSPLIT * B_TILE_BYTES;
#pragma unroll
        for (int k = 0; k < 8; k++) {              // 32KB bf16 B
            int off = (tid + k * 256) * 16;
            cpasync16(sdst + INC_STAGE_B + off, bb + off);
        }
        asm volatile("cp.async.commit_group;" ::: "memory");
    };

    // convert fp32 inc slab of chunk c -> bf16 A tile [e][m] swizzled, buffer c&1
    auto convert = [&](int c) {
        const float* sf = (const float*)(dsm + (c % 3) * STAGE_BYTES);
        char* ad = dsm + ABUF_OFF + (c & 1) * A_TILE_BYTES;
#pragma unroll
        for (int rep = 0; rep < 4; rep++) {
            int cid = tid + rep * 256;
            int erow = cid & 127, mb = cid >> 7;     // 128 e-rows x (2 of 8) m-blocks
            float f[8];
#pragma unroll
            for (int q = 0; q < 8; q++)
                f[q] = sf[(mb * 8 + q) * (INC_PITCH_B / 4) + erow];
            uint32_t p[4];
#pragma unroll
            for (int q = 0; q < 4; q++)
                asm("cvt.rn.bf16x2.f32 %0, %1, %2;" : "=r"(p[q]) : "f"(f[2 * q + 1]), "f"(f[2 * q]));
            uint32_t off = SWZ128((uint32_t)(erow * 128 + mb * 16));
            *(uint4*)(ad + off) = make_uint4(p[0], p[1], p[2], p[3]);
        }
    };

    float acc[4][4][4];
#pragma unroll
    for (int i = 0; i < 4; i++)
#pragma unroll
        for (int j = 0; j < 4; j++)
#pragma unroll
            for (int c = 0; c < 4; c++) acc[i][j][c] = 0.f;

    int a_row = warp_e * 64 + (lane & 15);
    int a_kb  = (lane >> 4) << 4;
    int b_row = warp_d * 32 + (lane & 7) + ((lane >> 4) << 3);
    int b_kb  = (lane & 8) * 2;

    stage_copy(0, kc0);
    stage_copy(1, kc0 + 1);
    stage_copy(2, kc0 + 2);
    asm volatile("cp.async.wait_group 2;" ::: "memory");   // chunk kc0 arrived
    __syncthreads();
    convert(0);                                            // A0 (visible after iter-0 sync)

    for (int i = 0; i < NCHUNK; i++) {
        // outstanding copies at top: chunks i+1, i+2 (where valid)
        if (i + 2 < NCHUNK)      { asm volatile("cp.async.wait_group 1;" ::: "memory"); }
        else if (i + 1 < NCHUNK) { asm volatile("cp.async.wait_group 0;" ::: "memory"); }
        __syncthreads();

        if (i + 1 < NCHUNK) convert(i + 1);   // interleaves with mma below (no sync)

        uint32_t sA = base + ABUF_OFF + (i & 1) * A_TILE_BYTES;
        uint32_t sB = base + (i % 3) * STAGE_BYTES + INC_STAGE_B;
#pragma unroll
        for (int t = 0; t < 4; t++) {
            uint32_t a[4][4];
#pragma unroll
            for (int ei = 0; ei < 4; ei++) {
                uint32_t off = (uint32_t)((a_row + ei * 16) * 128 + a_kb + t * 32);
                ldsm_x4(a[ei][0], a[ei][1], a[ei][2], a[ei][3], sA + SWZ128(off));
            }
#pragma unroll
            for (int s = 0; s < NSPLIT; s++) {
#pragma unroll
                for (int j = 0; j < 2; j++) {
                    uint32_t b0, b1, b2, b3;
                    uint32_t off = (uint32_t)((b_row + j * 16) * 128 + b_kb + t * 32);
                    ldsm_x4(b0, b1, b2, b3, sB + s * B_TILE_BYTES + SWZ128(off));
#pragma unroll
                    for (int ei = 0; ei < 4; ei++) {
                        mma16816(acc[ei][j * 2 + 0], a[ei][0], a[ei][1], a[ei][2], a[ei][3], b0, b1);
                        mma16816(acc[ei][j * 2 + 1], a[ei][0], a[ei][1], a[ei][2], a[ei][3], b2, b3);
                    }
                }
            }
        }
        __syncthreads();   // A[(i+1)&1] written & stage[i%3] drained
        if (i + 3 < NCHUNK) stage_copy(i % 3, kc0 + i + 3);
    }

    float* gout = g_aggp + (((size_t)kh * BB + b) * EE + et * 128) * DD;
    int gr = lane >> 2, gc = (lane & 3) * 2;
#pragma unroll
    for (int ei = 0; ei < 4; ei++) {
#pragma unroll
        for (int jj = 0; jj < 4; jj++) {
            int e_ = warp_e * 64 + ei * 16 + gr;
            int d_ = warp_d * 32 + jj * 8 + gc;
            *(float2*)(gout + (size_t)e_ * DD + d_) = make_float2(acc[ei][jj][0], acc[ei][jj][1]);
            *(float2*)(gout + (size_t)(e_ + 8) * DD + d_) = make_float2(acc[ei][jj][2], acc[ei][jj][3]);
        }
    }
}

// ---- rowgemm on agg = aggp0+aggp1, 32-row tiles (grid 256 for occupancy)
// PHASE 0: esc GEMM (Wt_att) -> stores w=exp(esc) + per-block column partials
// PHASE 1: edgefeat GEMM on (agg * w * invcolsum) (Wt_proj), fused pooling.
template <int PHASE>
__global__ __launch_bounds__(256) void rowgemm(const float* __restrict__ attw) {
    __shared__ float WtS[32 * 128];
    __shared__ float fsh[RG_ROWS * 33];
    __shared__ __align__(16) float sICS[128];
    __shared__ float redc[8 * 128];
    __shared__ float sden[8];
    const float* __restrict__ X0 = g_aggp;
    const float* __restrict__ X1 = g_aggp + (size_t)BB * EE * DD;
    const float* __restrict__ Wt = (PHASE == 0) ? g_Wt_att : g_Wt_proj;

    int tid = threadIdx.x;
    int tx = tid & 31, ty = tid >> 5;
    int row0 = blockIdx.x * RG_ROWS;
    int bb = blockIdx.x >> 5;     // 32 blocks per batch

    if (PHASE == 1) {   // finish column-softmax denominators -> inverse, in smem
        if (tid < 128) {
            float t = 0.f;
#pragma unroll
            for (int blk = 0; blk < 32; blk++) t += g_colpart[(bb * 32 + blk) * 128 + tid];
            sICS[tid] = 1.f / t;
        }
        __syncthreads();
    }

    float acc[4][4];
#pragma unroll
    for (int i = 0; i < 4; i++)
#pragma unroll
        for (int c = 0; c < 4; c++) acc[i][c] = 0.f;

    for (int kc = 0; kc < DD; kc += 32) {
#pragma unroll
        for (int i = 0; i < 4; i++) {
            int slot = tid + i * 256;
            int k = slot >> 5, j4 = slot & 31;
            *reinterpret_cast<float4*>(&WtS[k * 128 + j4 * 4]) =
                *reinterpret_cast<const float4*>(&Wt[(kc + k) * DD + j4 * 4]);
        }
        {
            int r = tid >> 3, kq = tid & 7;
            size_t idx = (size_t)(row0 + r) * DD + kc + kq * 4;
            float4 v0 = *reinterpret_cast<const float4*>(&X0[idx]);
            float4 v1 = *reinterpret_cast<const float4*>(&X1[idx]);
            float fx = v0.x + v1.x, fy = v0.y + v1.y, fz = v0.z + v1.z, fw = v0.w + v1.w;
            if (PHASE == 1) {
                float4 w = *reinterpret_cast<const float4*>(&g_esc[idx]);
                float4 ic = *reinterpret_cast<const float4*>(&sICS[kc + kq * 4]);
                fx *= w.x * ic.x; fy *= w.y * ic.y; fz *= w.z * ic.z; fw *= w.w * ic.w;
            }
            fsh[r * 33 + kq * 4 + 0] = fx; fsh[r * 33 + kq * 4 + 1] = fy;
            fsh[r * 33 + kq * 4 + 2] = fz; fsh[r * 33 + kq * 4 + 3] = fw;
        }
        __syncthreads();
#pragma unroll
        for (int k = 0; k < 32; k++) {
            float4 w4 = *reinterpret_cast<const float4*>(&WtS[k * 128 + tx * 4]);
#pragma unroll
            for (int i = 0; i < 4; i++) {
                float f = fsh[(ty * 4 + i) * 33 + k];
                acc[i][0] = fmaf(f, w4.x, acc[i][0]);
                acc[i][1] = fmaf(f, w4.y, acc[i][1]);
                acc[i][2] = fmaf(f, w4.z, acc[i][2]);
                acc[i][3] = fmaf(f, w4.w, acc[i][3]);
            }
        }
        __syncthreads();
    }

    if (PHASE == 0) {
        float colp[4] = {0.f, 0.f, 0.f, 0.f};
#pragma unroll
        for (int i = 0; i < 4; i++) {
            int r = row0 + ty * 4 + i;
#pragma unroll
            for (int c = 0; c < 4; c++) {
                float w = __expf(acc[i][c]);
                acc[i][c] = w;
                colp[c] += w;
            }
            *reinterpret_cast<float4*>(&g_esc[(size_t)r * DD + tx * 4]) =
                make_float4(acc[i][0], acc[i][1], acc[i][2], acc[i][3]);
        }
        *reinterpret_cast<float4*>(&redc[ty * 128 + tx * 4]) =
            make_float4(colp[0], colp[1], colp[2], colp[3]);
        __syncthreads();
        if (ty == 0) {
#pragma unroll
            for (int c = 0; c < 4; c++) {
                float s = 0.f;
#pragma unroll
                for (int t = 0; t < 8; t++) s += redc[t * 128 + tx * 4 + c];
                g_colpart[blockIdx.x * 128 + tx * 4 + c] = s;
            }
        }
    } else {
        float4 aw = *reinterpret_cast<const float4*>(&attw[tx * 4]);
        float pacc[4] = {0.f, 0.f, 0.f, 0.f};
        float dacc = 0.f;
#pragma unroll
        for (int i = 0; i < 4; i++) {
            float4 v = make_float4(acc[i][0], acc[i][1], acc[i][2], acc[i][3]);
            float p = v.x * aw.x + v.y * aw.y + v.z * aw.z + v.w * aw.w;
#pragma unroll
            for (int off = 16; off > 0; off >>= 1)
                p += __shfl_xor_sync(0xffffffffu, p, off);
            float wv = __expf(p);
            pacc[0] = fmaf(v.x, wv, pacc[0]); pacc[1] = fmaf(v.y, wv, pacc[1]);
            pacc[2] = fmaf(v.z, wv, pacc[2]); pacc[3] = fmaf(v.w, wv, pacc[3]);
            dacc += wv;
        }
        *reinterpret_cast<float4*>(&redc[ty * 128 + tx * 4]) =
            make_float4(pacc[0], pacc[1], pacc[2], pacc[3]);
        if (tx == 0) sden[ty] = dacc;
        __syncthreads();
        if (ty == 0) {
#pragma unroll
            for (int c = 0; c < 4; c++) {
                float s = 0.f;
#pragma unroll
                for (int t = 0; t < 8; t++) s += redc[t * 128 + tx * 4 + c];
                g_poolpart[blockIdx.x * 128 + tx * 4 + c] = s;
            }
        }
        if (tid == 0) {
            float s = 0.f;
#pragma unroll
            for (int t = 0; t < 8; t++) s += sden[t];
            g_poolden[blockIdx.x] = s;
        }
    }
}

// ---- K5: pooled = numer/S; out = pooled@ec_proj^T + b; logits = out@fc^T + fc_b ----
__global__ __launch_bounds__(128) void pool_head(const float* __restrict__ ec_proj_w,
                                                 const float* __restrict__ ec_proj_b,
                                                 const float* __restrict__ fc_w,
                                                 const float* __restrict__ fc_b,
                                                 float* __restrict__ out) {
    int b = blockIdx.x, d = threadIdx.x;
    __shared__ float p[DD];
    __shared__ float o[DD];
    float n = 0.f, S = 0.f;
#pragma unroll
    for (int blk = 0; blk < 32; blk++) {
        n += g_poolpart[(b * 32 + blk) * 128 + d];
        S += g_poolden[b * 32 + blk];
    }
    p[d] = n / S;
    __syncthreads();
    float acc = ec_proj_b[d];
#pragma unroll 4
    for (int k = 0; k < DD; k++) acc = fmaf(p[k], ec_proj_w[d * DD + k], acc);
    o[d] = acc;
    __syncthreads();
    if (d < NCAT) {
        float l = fc_b[d];
#pragma unroll 4
        for (int k = 0; k < DD; k++) l = fmaf(o[k], fc_w[d * DD + k], l);
        out[b * NCAT + d] = l;
    }
}

// ---- launch ----
extern "C" void kernel_launch(void* const* d_in, const int* in_sizes, int n_in,
                              void* d_out, int out_size) {
    const float* node_feats = (const float*)d_in[0];
    const float* inc_mat    = (const float*)d_in[1];
    const float* W_att      = (const float*)d_in[2];
    const float* W_proj     = (const float*)d_in[3];
    const float* ec_att_w   = (const float*)d_in[4];
    const float* ec_proj_w  = (const float*)d_in[5];
    const float* ec_proj_b  = (const float*)d_in[6];
    const float* fc_w       = (const float*)d_in[7];
    const float* fc_b       = (const float*)d_in[8];
    float* out = (float*)d_out;

    cudaFuncSetAttribute(mma_agg_kernel, cudaFuncAttributeMaxDynamicSharedMemorySize, DYN_SMEM);

    conv_feats<<<dim3(NKC, BB + 1), 256>>>(node_feats, W_att, W_proj);
    mma_agg_kernel<<<dim3(8, BB, NKH), 256, DYN_SMEM>>>(inc_mat);
    rowgemm<0><<<NRGB, 256>>>(nullptr);               // w=exp(esc) + column partials
    rowgemm<1><<<NRGB, 256>>>(ec_att_w);              // fused inv-colsum + pooling
    pool_head<<<BB, 128>>>(ec_proj_w, ec_proj_b, fc_w, fc_b, out);
}